// round 9
// baseline (speedup 1.0000x reference)
#include <cuda_runtime.h>
#include <cuda_fp16.h>
#include <cstdint>

#define B_DIM 4
#define T_DIM 4096
#define D_DIM 1024
#define HS 64
#define PB 72      // fp16 pitch: conflict-free frag loads, 16B-aligned rows
#define QBLK 128   // q rows per attn CTA
#define NCHUNK 8   // max kv chunks per q-block
#define CBLK 8     // kv blocks (of 64 keys) per chunk

// Projected tensors (fp16). K: hi only. QV: hi/lo. QV^T: hi/lo.
__device__ __align__(16) uint16_t g_kh[B_DIM * T_DIM * HS];
__device__ __align__(16) uint16_t g_qh[B_DIM * T_DIM * HS];
__device__ __align__(16) uint16_t g_ql[B_DIM * T_DIM * HS];
__device__ __align__(16) uint16_t g_vth[B_DIM * HS * T_DIM];  // QV^T [b][h][t]
__device__ __align__(16) uint16_t g_vtl[B_DIM * HS * T_DIM];

// Preconverted weights: Wk hi; Wv hi/lo
__device__ __align__(16) uint16_t g_wkh[HS * D_DIM];
__device__ __align__(16) uint16_t g_wvh[HS * D_DIM];
__device__ __align__(16) uint16_t g_wvl[HS * D_DIM];

// Split-KV partials: unit = (b*32 + mblk)*NCHUNK + chunk, 128 rows each
__device__ __align__(16) uint16_t g_po[B_DIM * 32 * NCHUNK * QBLK * HS];  // fp16
__device__ float g_pm[B_DIM * 32 * NCHUNK * QBLK];
__device__ float g_pl[B_DIM * 32 * NCHUNK * QBLK];

#define CSC 0.1803368801111204f  // 0.125 * log2(e)

__device__ __forceinline__ uint32_t hpack(float a, float b) {
    __half2 hh = __floats2half2_rn(a, b);
    return *(uint32_t*)&hh;
}
__device__ __forceinline__ void packpair(float a, float b, uint32_t& h, uint32_t& l) {
    __half2 hh = __floats2half2_rn(a, b);
    h = *(uint32_t*)&hh;
    float2 fb = __half22float2(hh);
    l = hpack(a - fb.x, b - fb.y);
}
__device__ __forceinline__ void mma_f16(float* c, uint32_t a0, uint32_t a1,
                                        uint32_t a2, uint32_t a3,
                                        uint32_t b0, uint32_t b1) {
    asm volatile(
        "mma.sync.aligned.m16n8k16.row.col.f32.f16.f16.f32 "
        "{%0,%1,%2,%3}, {%4,%5,%6,%7}, {%8,%9}, {%0,%1,%2,%3};"
        : "+f"(c[0]), "+f"(c[1]), "+f"(c[2]), "+f"(c[3])
        : "r"(a0), "r"(a1), "r"(a2), "r"(a3), "r"(b0), "r"(b1));
}
__device__ __forceinline__ void sstore2(uint16_t* Sh, uint16_t* Sl, int off,
                                        float a, float b) {
    uint32_t h, l;
    packpair(a, b, h, l);
    *(uint32_t*)&Sh[off] = h;
    *(uint32_t*)&Sl[off] = l;
}
__device__ __forceinline__ void cpa16(uint32_t dst, const void* src) {
    asm volatile("cp.async.cg.shared.global [%0], [%1], 16;" :: "r"(dst), "l"(src));
}
#define LD32(arr, idx) (*(const uint32_t*)&(arr)[idx])

// ---------------------------------------------------------------------------
// One-time weight conversion fp32 -> fp16 (Wk hi; Wv hi/lo)
// ---------------------------------------------------------------------------
__global__ __launch_bounds__(256) void wconv_kernel(const float* __restrict__ Wk,
                                                    const float* __restrict__ Wv) {
    int i = blockIdx.x * 512 + threadIdx.x * 2;
    *(uint32_t*)&g_wkh[i] = hpack(Wk[i], Wk[i + 1]);
    uint32_t h, l;
    packpair(Wv[i], Wv[i + 1], h, l);
    *(uint32_t*)&g_wvh[i] = h;
    *(uint32_t*)&g_wvl[i] = l;
}

// ---------------------------------------------------------------------------
// Projection, 128-row CTAs, 256 thr: k = x@Wk^T (1-MMA), qv = x@Wv^T (3-MMA).
// ---------------------------------------------------------------------------
__global__ __launch_bounds__(256, 2) void proj_kernel(const float* __restrict__ x) {
    extern __shared__ __align__(16) uint16_t sm[];
    uint16_t* sXh = sm;                       // [128][PB]
    uint16_t* sXl = sXh + 128 * PB;
    uint16_t* sWk = sXl + 128 * PB;           // [64][PB]
    uint16_t* sWvh = sWk + 64 * PB;
    uint16_t* sWvl = sWvh + 64 * PB;
    const uint32_t smb = (uint32_t)__cvta_generic_to_shared(sm);
    const uint32_t XAB = 128 * PB * 2;
    const uint32_t WAB = 64 * PB * 2;

    const int tid = threadIdx.x;
    const int w = tid >> 5, lane = tid & 31, g = lane >> 2, t = lane & 3;
    const int RB = blockIdx.x * 128;
    const int m0 = w * 16;

    float accK[8][4] = {};
    float accV[8][4] = {};

    for (int d0 = 0; d0 < D_DIM; d0 += 64) {
        __syncthreads();
        // W tiles via cp.async: 3 arrays x 512 16B-chunks / 256 thr
        #pragma unroll
        for (int l = 0; l < 2; ++l) {
            int id = tid + l * 256;
            int r = id >> 3, c8 = (id & 7) * 8;
            uint32_t soff = (uint32_t)(r * PB + c8) * 2;
            size_t go = (size_t)r * D_DIM + d0 + c8;
            cpa16(smb + 2 * XAB + soff, &g_wkh[go]);
            cpa16(smb + 2 * XAB + WAB + soff, &g_wvh[go]);
            cpa16(smb + 2 * XAB + 2 * WAB + soff, &g_wvl[go]);
        }
        asm volatile("cp.async.commit_group;");
        // x tile (128 rows): fp32 -> fp16 hi/lo
        #pragma unroll
        for (int l = 0; l < 8; ++l) {
            int idx = tid + l * 256;          // float4 index 0..2047
            int r = idx >> 4, c = (idx & 15) * 4;
            float4 fx = *(const float4*)&x[(size_t)(RB + r) * D_DIM + d0 + c];
            sstore2(sXh, sXl, r * PB + c, fx.x, fx.y);
            sstore2(sXh, sXl, r * PB + c + 2, fx.z, fx.w);
        }
        asm volatile("cp.async.wait_group 0;" ::: "memory");
        __syncthreads();

        #pragma unroll
        for (int k0 = 0; k0 < 64; k0 += 16) {
            int ra = (m0 + g) * PB + k0 + 2 * t;
            uint32_t ah0 = LD32(sXh, ra);
            uint32_t ah1 = LD32(sXh, ra + 8 * PB);
            uint32_t ah2 = LD32(sXh, ra + 8);
            uint32_t ah3 = LD32(sXh, ra + 8 * PB + 8);
            uint32_t al0 = LD32(sXl, ra);
            uint32_t al1 = LD32(sXl, ra + 8 * PB);
            uint32_t al2 = LD32(sXl, ra + 8);
            uint32_t al3 = LD32(sXl, ra + 8 * PB + 8);
            #pragma unroll
            for (int j = 0; j < 8; ++j) {
                int rb = (8 * j + g) * PB + k0 + 2 * t;
                uint32_t k0r = LD32(sWk, rb), k1r = LD32(sWk, rb + 8);
                mma_f16(accK[j], ah0, ah1, ah2, ah3, k0r, k1r);
                uint32_t vh0 = LD32(sWvh, rb), vh1 = LD32(sWvh, rb + 8);
                uint32_t vl0 = LD32(sWvl, rb), vl1 = LD32(sWvl, rb + 8);
                mma_f16(accV[j], ah0, ah1, ah2, ah3, vh0, vh1);
                mma_f16(accV[j], ah0, ah1, ah2, ah3, vl0, vl1);
                mma_f16(accV[j], al0, al1, al2, al3, vh0, vh1);
            }
        }
    }

    const int row0 = RB + m0 + g;
    const int batch = row0 / T_DIM;
    const int tl0 = row0 % T_DIM;

    #pragma unroll
    for (int j = 0; j < 8; ++j) {
        int col = 8 * j + 2 * t;
        *(uint32_t*)&g_kh[(size_t)row0 * HS + col] = hpack(accK[j][0], accK[j][1]);
        *(uint32_t*)&g_kh[(size_t)(row0 + 8) * HS + col] = hpack(accK[j][2], accK[j][3]);
        uint32_t h, l;
        packpair(accV[j][0], accV[j][1], h, l);
        *(uint32_t*)&g_qh[(size_t)row0 * HS + col] = h;
        *(uint32_t*)&g_ql[(size_t)row0 * HS + col] = l;
        packpair(accV[j][2], accV[j][3], h, l);
        *(uint32_t*)&g_qh[(size_t)(row0 + 8) * HS + col] = h;
        *(uint32_t*)&g_ql[(size_t)(row0 + 8) * HS + col] = l;
        #pragma unroll
        for (int q = 0; q < 4; ++q) {
            float v = accV[j][q];
            int cc = col + (q & 1);
            int tt = tl0 + (q >> 1) * 8;
            __half hv = __float2half_rn(v);
            __half lv = __float2half_rn(v - __half2float(hv));
            size_t off = ((size_t)batch * HS + cc) * T_DIM + tt;
            g_vth[off] = *(uint16_t*)&hv;
            g_vtl[off] = *(uint16_t*)&lv;
        }
    }
}

// ---------------------------------------------------------------------------
// Split-KV flash attention, QBLK=128. Partial O stored fp16.
// ---------------------------------------------------------------------------
#define ABYTES (64 * PB * 2)
#define BUFBYTES (3 * ABYTES)
#define AU16 (64 * PB)

__global__ __launch_bounds__(128, 2) void attn_kernel() {
    const int mblk = 31 - blockIdx.x;          // longest-first
    const int kbLast = 2 * mblk + 1;
    const int kb0 = blockIdx.y * CBLK;
    if (kb0 > kbLast) return;
    const int kb1 = min(kb0 + CBLK - 1, kbLast);
    const int b = blockIdx.z;
    const int unit = (b * 32 + mblk) * NCHUNK + blockIdx.y;

    extern __shared__ __align__(16) uint16_t sm[];
    const uint32_t smb = (uint32_t)__cvta_generic_to_shared(sm);

    const int tid = threadIdx.x;
    const int w = tid >> 5, lane = tid & 31, g = lane >> 2, t = lane & 3;
    const int qRow = mblk * QBLK;
    const int m0 = w * 32;
    const int lr = tid >> 3;
    const int lc = (tid & 7) * 8;

    // Q A-fragments (single fp16), two row tiles
    uint32_t q[2][4][4];
    {
        const uint16_t* Qh = g_qh + (size_t)b * T_DIM * HS;
        #pragma unroll
        for (int tt = 0; tt < 2; ++tt) {
            int base = (qRow + m0 + tt * 16 + g) * HS + 2 * t;
            #pragma unroll
            for (int kk = 0; kk < 4; ++kk) {
                int o = base + kk * 16;
                q[tt][kk][0] = LD32(Qh, o);
                q[tt][kk][1] = LD32(Qh, o + 8 * HS);
                q[tt][kk][2] = LD32(Qh, o + 8);
                q[tt][kk][3] = LD32(Qh, o + 8 * HS + 8);
            }
        }
    }

    auto issue_tile = [&](int buf, int kb) {
        uint32_t base = smb + buf * BUFBYTES;
        #pragma unroll
        for (int l = 0; l < 4; ++l) {
            int r = lr + l * 16;
            uint32_t soff = (uint32_t)(r * PB + lc) * 2;
            size_t gk = ((size_t)b * T_DIM + kb * 64 + r) * HS + lc;
            cpa16(base + soff, &g_kh[gk]);
            size_t gv = ((size_t)b * HS + r) * T_DIM + kb * 64 + lc;
            cpa16(base + ABYTES + soff, &g_vth[gv]);
            cpa16(base + 2 * ABYTES + soff, &g_vtl[gv]);
        }
        asm volatile("cp.async.commit_group;");
    };

    issue_tile(kb0 & 1, kb0);

    float acc[2][8][4] = {};
    float mrow[4] = {-1e30f, -1e30f, -1e30f, -1e30f};
    float lrow[4] = {0.f, 0.f, 0.f, 0.f};

    for (int kb = kb0; kb <= kb1; ++kb) {
        asm volatile("cp.async.wait_group 0;" ::: "memory");
        __syncthreads();
        if (kb < kb1) issue_tile((kb + 1) & 1, kb + 1);

        const uint16_t* bKh = sm + (kb & 1) * 3 * AU16;
        const uint16_t* bVh = bKh + AU16;
        const uint16_t* bVl = bKh + 2 * AU16;

        // S = Q @ K^T for both row tiles
        float s[2][8][4] = {};
        #pragma unroll
        for (int kk = 0; kk < 4; ++kk) {
            #pragma unroll
            for (int j = 0; j < 8; ++j) {
                int rb = (8 * j + g) * PB + kk * 16 + 2 * t;
                uint32_t b0 = LD32(bKh, rb), b1 = LD32(bKh, rb + 8);
                mma_f16(s[0][j], q[0][kk][0], q[0][kk][1], q[0][kk][2], q[0][kk][3], b0, b1);
                mma_f16(s[1][j], q[1][kk][0], q[1][kk][1], q[1][kk][2], q[1][kk][3], b0, b1);
            }
        }

        // causal mask: only last two kv blocks overlap the diagonal
        if (kb >= 2 * mblk) {
            const int off = qRow - kb * 64;
            #pragma unroll
            for (int tt = 0; tt < 2; ++tt) {
                int r0l = m0 + tt * 16 + g + off, r1l = r0l + 8;
                #pragma unroll
                for (int j = 0; j < 8; ++j) {
                    int c0 = 8 * j + 2 * t, c1 = c0 + 1;
                    if (c0 > r0l) s[tt][j][0] = -1e30f;
                    if (c1 > r0l) s[tt][j][1] = -1e30f;
                    if (c0 > r1l) s[tt][j][2] = -1e30f;
                    if (c1 > r1l) s[tt][j][3] = -1e30f;
                }
            }
        }

        #pragma unroll
        for (int tt = 0; tt < 2; ++tt) {
            float mx0 = -1e30f, mx1 = -1e30f;
            #pragma unroll
            for (int j = 0; j < 8; ++j) {
                mx0 = fmaxf(mx0, fmaxf(s[tt][j][0], s[tt][j][1]));
                mx1 = fmaxf(mx1, fmaxf(s[tt][j][2], s[tt][j][3]));
            }
            mx0 = fmaxf(mx0, __shfl_xor_sync(0xffffffffu, mx0, 1));
            mx0 = fmaxf(mx0, __shfl_xor_sync(0xffffffffu, mx0, 2));
            mx1 = fmaxf(mx1, __shfl_xor_sync(0xffffffffu, mx1, 1));
            mx1 = fmaxf(mx1, __shfl_xor_sync(0xffffffffu, mx1, 2));
            float mn0 = fmaxf(mrow[tt * 2], mx0), mn1 = fmaxf(mrow[tt * 2 + 1], mx1);
            float cr0 = exp2f((mrow[tt * 2] - mn0) * CSC);
            float cr1 = exp2f((mrow[tt * 2 + 1] - mn1) * CSC);
            float sum0 = 0.f, sum1 = 0.f;
            #pragma unroll
            for (int j = 0; j < 8; ++j) {
                s[tt][j][0] = exp2f((s[tt][j][0] - mn0) * CSC);
                s[tt][j][1] = exp2f((s[tt][j][1] - mn0) * CSC);
                s[tt][j][2] = exp2f((s[tt][j][2] - mn1) * CSC);
                s[tt][j][3] = exp2f((s[tt][j][3] - mn1) * CSC);
                sum0 += s[tt][j][0] + s[tt][j][1];
                sum1 += s[tt][j][2] + s[tt][j][3];
            }
            sum0 += __shfl_xor_sync(0xffffffffu, sum0, 1);
            sum0 += __shfl_xor_sync(0xffffffffu, sum0, 2);
            sum1 += __shfl_xor_sync(0xffffffffu, sum1, 1);
            sum1 += __shfl_xor_sync(0xffffffffu, sum1, 2);
            lrow[tt * 2] = lrow[tt * 2] * cr0 + sum0;
            lrow[tt * 2 + 1] = lrow[tt * 2 + 1] * cr1 + sum1;
            mrow[tt * 2] = mn0;
            mrow[tt * 2 + 1] = mn1;
            #pragma unroll
            for (int j = 0; j < 8; ++j) {
                acc[tt][j][0] *= cr0;
                acc[tt][j][1] *= cr0;
                acc[tt][j][2] *= cr1;
                acc[tt][j][3] *= cr1;
            }
        }

        // P (hi only) x V hi/lo for both row tiles
        #pragma unroll
        for (int kk = 0; kk < 4; ++kk) {
            uint32_t ph[2][4];
            #pragma unroll
            for (int tt = 0; tt < 2; ++tt) {
                float* pA = s[tt][2 * kk];
                float* pB = s[tt][2 * kk + 1];
                ph[tt][0] = hpack(pA[0], pA[1]);
                ph[tt][1] = hpack(pA[2], pA[3]);
                ph[tt][2] = hpack(pB[0], pB[1]);
                ph[tt][3] = hpack(pB[2], pB[3]);
            }
            #pragma unroll
            for (int j = 0; j < 8; ++j) {
                int rb = (8 * j + g) * PB + kk * 16 + 2 * t;
                uint32_t vh0 = LD32(bVh, rb), vh1 = LD32(bVh, rb + 8);
                uint32_t vl0 = LD32(bVl, rb), vl1 = LD32(bVl, rb + 8);
                mma_f16(acc[0][j], ph[0][0], ph[0][1], ph[0][2], ph[0][3], vh0, vh1);
                mma_f16(acc[0][j], ph[0][0], ph[0][1], ph[0][2], ph[0][3], vl0, vl1);
                mma_f16(acc[1][j], ph[1][0], ph[1][1], ph[1][2], ph[1][3], vh0, vh1);
                mma_f16(acc[1][j], ph[1][0], ph[1][1], ph[1][2], ph[1][3], vl0, vl1);
            }
        }
    }

    // write partials (O as fp16)
    if (t == 0) {
        #pragma unroll
        for (int tt = 0; tt < 2; ++tt) {
            int r = m0 + tt * 16 + g;
            g_pm[(size_t)unit * QBLK + r] = mrow[tt * 2];
            g_pm[(size_t)unit * QBLK + r + 8] = mrow[tt * 2 + 1];
            g_pl[(size_t)unit * QBLK + r] = lrow[tt * 2];
            g_pl[(size_t)unit * QBLK + r + 8] = lrow[tt * 2 + 1];
        }
    }
    #pragma unroll
    for (int tt = 0; tt < 2; ++tt) {
        int r = m0 + tt * 16 + g;
        #pragma unroll
        for (int j = 0; j < 8; ++j) {
            int col = 8 * j + 2 * t;
            size_t pbase = ((size_t)unit * QBLK + r) * HS + col;
            *(uint32_t*)&g_po[pbase] = hpack(acc[tt][j][0], acc[tt][j][1]);
            *(uint32_t*)&g_po[pbase + 8 * HS] = hpack(acc[tt][j][2], acc[tt][j][3]);
        }
    }
}

// ---------------------------------------------------------------------------
// Combine fp16 partials. Grid (32, B, 8): blockIdx.z = 8-col octet.
// ---------------------------------------------------------------------------
__global__ __launch_bounds__(256) void reduce_kernel(float* __restrict__ out) {
    const int mb = blockIdx.x, b = blockIdx.y;
    const int nc = (2 * mb + 2 + CBLK - 1) / CBLK;
    const int tid = threadIdx.x;
    const int r = tid >> 1;
    const int col = blockIdx.z * 8 + (tid & 1) * 4;
    const size_t ubase = ((size_t)(b * 32 + mb)) * NCHUNK;

    float m[NCHUNK], wgt[NCHUNK];
    float mstar = -1e30f;
    #pragma unroll
    for (int c = 0; c < NCHUNK; ++c) {
        if (c < nc) {
            m[c] = g_pm[(ubase + c) * QBLK + r];
            mstar = fmaxf(mstar, m[c]);
        }
    }
    float lsum = 0.f;
    #pragma unroll
    for (int c = 0; c < NCHUNK; ++c) {
        if (c < nc) {
            wgt[c] = exp2f((m[c] - mstar) * CSC);
            lsum += wgt[c] * g_pl[(ubase + c) * QBLK + r];
        }
    }
    float inv = 1.f / lsum;

    float4 o = make_float4(0.f, 0.f, 0.f, 0.f);
    #pragma unroll
    for (int c = 0; c < NCHUNK; ++c) {
        if (c < nc) {
            uint2 pk = *(const uint2*)&g_po[((ubase + c) * QBLK + r) * HS + col];
            float2 p01 = __half22float2(*(__half2*)&pk.x);
            float2 p23 = __half22float2(*(__half2*)&pk.y);
            o.x += wgt[c] * p01.x;
            o.y += wgt[c] * p01.y;
            o.z += wgt[c] * p23.x;
            o.w += wgt[c] * p23.y;
        }
    }
    *(float4*)&out[((size_t)b * T_DIM + mb * QBLK + r) * HS + col] =
        make_float4(o.x * inv, o.y * inv, o.z * inv, o.w * inv);
}

extern "C" void kernel_launch(void* const* d_in, const int* in_sizes, int n_in,
                              void* d_out, int out_size) {
    const float* x = (const float*)d_in[0];
    const float* Wk = (const float*)d_in[1];
    const float* Wv = (const float*)d_in[2];
    float* out = (float*)d_out;

    const int smemProj = (2 * 128 + 3 * 64) * PB * sizeof(uint16_t);  // 64512
    const int smemAttn = 2 * BUFBYTES;                                // 55296
    cudaFuncSetAttribute(proj_kernel, cudaFuncAttributeMaxDynamicSharedMemorySize, smemProj);
    cudaFuncSetAttribute(attn_kernel, cudaFuncAttributeMaxDynamicSharedMemorySize, smemAttn);

    wconv_kernel<<<HS * D_DIM / 512, 256>>>(Wk, Wv);
    proj_kernel<<<(B_DIM * T_DIM) / 128, 256, smemProj>>>(x);
    attn_kernel<<<dim3(32, NCHUNK, B_DIM), 128, smemAttn>>>();
    reduce_kernel<<<dim3(32, B_DIM, 8), 256>>>(out);
}

// round 10
// speedup vs baseline: 1.1005x; 1.1005x over previous
#include <cuda_runtime.h>
#include <cuda_fp16.h>
#include <cstdint>

#define B_DIM 4
#define T_DIM 4096
#define D_DIM 1024
#define HS 64
#define PB 72      // fp16 pitch: conflict-free frag loads, 16B-aligned rows
#define QBLK 128   // q rows per attn CTA
#define NCHUNK 8   // max kv chunks per q-block
#define CBLK 8     // kv blocks (of 64 keys) per chunk

// Projected tensors (fp16). K: hi only. Q(=QV) hi only. QV^T: hi/lo.
__device__ __align__(16) uint16_t g_kh[B_DIM * T_DIM * HS];
__device__ __align__(16) uint16_t g_qh[B_DIM * T_DIM * HS];
__device__ __align__(16) uint16_t g_vth[B_DIM * HS * T_DIM];  // QV^T [b][h][t]
__device__ __align__(16) uint16_t g_vtl[B_DIM * HS * T_DIM];

// Preconverted weights: Wk hi; Wv hi/lo
__device__ __align__(16) uint16_t g_wkh[HS * D_DIM];
__device__ __align__(16) uint16_t g_wvh[HS * D_DIM];
__device__ __align__(16) uint16_t g_wvl[HS * D_DIM];

// Split-KV partials: unit = (b*32 + mblk)*NCHUNK + chunk, 128 rows each
__device__ __align__(16) uint16_t g_po[B_DIM * 32 * NCHUNK * QBLK * HS];  // fp16
__device__ float g_pm[B_DIM * 32 * NCHUNK * QBLK];
__device__ float g_pl[B_DIM * 32 * NCHUNK * QBLK];

#define CSC 0.1803368801111204f  // 0.125 * log2(e)

__device__ __forceinline__ uint32_t hpack(float a, float b) {
    __half2 hh = __floats2half2_rn(a, b);
    return *(uint32_t*)&hh;
}
__device__ __forceinline__ void packpair(float a, float b, uint32_t& h, uint32_t& l) {
    __half2 hh = __floats2half2_rn(a, b);
    h = *(uint32_t*)&hh;
    float2 fb = __half22float2(hh);
    l = hpack(a - fb.x, b - fb.y);
}
__device__ __forceinline__ void mma_f16(float* c, uint32_t a0, uint32_t a1,
                                        uint32_t a2, uint32_t a3,
                                        uint32_t b0, uint32_t b1) {
    asm volatile(
        "mma.sync.aligned.m16n8k16.row.col.f32.f16.f16.f32 "
        "{%0,%1,%2,%3}, {%4,%5,%6,%7}, {%8,%9}, {%0,%1,%2,%3};"
        : "+f"(c[0]), "+f"(c[1]), "+f"(c[2]), "+f"(c[3])
        : "r"(a0), "r"(a1), "r"(a2), "r"(a3), "r"(b0), "r"(b1));
}
__device__ __forceinline__ void sstore2(uint16_t* Sh, uint16_t* Sl, int off,
                                        float a, float b) {
    uint32_t h, l;
    packpair(a, b, h, l);
    *(uint32_t*)&Sh[off] = h;
    *(uint32_t*)&Sl[off] = l;
}
__device__ __forceinline__ void cpa16(uint32_t dst, const void* src) {
    asm volatile("cp.async.cg.shared.global [%0], [%1], 16;" :: "r"(dst), "l"(src));
}
#define LD32(arr, idx) (*(const uint32_t*)&(arr)[idx])

// ---------------------------------------------------------------------------
// One-time weight conversion fp32 -> fp16 (Wk hi; Wv hi/lo)
// ---------------------------------------------------------------------------
__global__ __launch_bounds__(256) void wconv_kernel(const float* __restrict__ Wk,
                                                    const float* __restrict__ Wv) {
    int i = blockIdx.x * 512 + threadIdx.x * 2;
    *(uint32_t*)&g_wkh[i] = hpack(Wk[i], Wk[i + 1]);
    uint32_t h, l;
    packpair(Wv[i], Wv[i + 1], h, l);
    *(uint32_t*)&g_wvh[i] = h;
    *(uint32_t*)&g_wvl[i] = l;
}

// ---------------------------------------------------------------------------
// Projection (R7 config): 64-row CTAs, 128 thr, 3 CTAs/SM.
// k = x@Wk^T (1-MMA), qv = x@Wv^T (3-MMA). W via cp.async.
// ---------------------------------------------------------------------------
__global__ __launch_bounds__(128, 3) void proj_kernel(const float* __restrict__ x) {
    extern __shared__ __align__(16) uint16_t sm[];
    uint16_t* sXh = sm;
    uint16_t* sXl = sXh + 64 * PB;
    uint16_t* sWk = sXl + 64 * PB;
    uint16_t* sWvh = sWk + 64 * PB;
    uint16_t* sWvl = sWvh + 64 * PB;
    const uint32_t smb = (uint32_t)__cvta_generic_to_shared(sm);
    const uint32_t AB = 64 * PB * 2;

    const int tid = threadIdx.x;
    const int w = tid >> 5, lane = tid & 31, g = lane >> 2, t = lane & 3;
    const int RB = blockIdx.x * 64;
    const int m0 = w * 16;

    float accK[8][4] = {};
    float accV[8][4] = {};

    for (int d0 = 0; d0 < D_DIM; d0 += 64) {
        __syncthreads();
        #pragma unroll
        for (int l = 0; l < 4; ++l) {
            int id = tid + l * 128;
            int r = id >> 3, c8 = (id & 7) * 8;
            uint32_t soff = (uint32_t)(r * PB + c8) * 2;
            size_t go = (size_t)r * D_DIM + d0 + c8;
            cpa16(smb + 2 * AB + soff, &g_wkh[go]);
            cpa16(smb + 3 * AB + soff, &g_wvh[go]);
            cpa16(smb + 4 * AB + soff, &g_wvl[go]);
        }
        asm volatile("cp.async.commit_group;");
        #pragma unroll
        for (int l = 0; l < 8; ++l) {
            int idx = tid + l * 128;
            int r = idx >> 4, c = (idx & 15) * 4;
            float4 fx = *(const float4*)&x[(size_t)(RB + r) * D_DIM + d0 + c];
            sstore2(sXh, sXl, r * PB + c, fx.x, fx.y);
            sstore2(sXh, sXl, r * PB + c + 2, fx.z, fx.w);
        }
        asm volatile("cp.async.wait_group 0;" ::: "memory");
        __syncthreads();

        #pragma unroll
        for (int k0 = 0; k0 < 64; k0 += 16) {
            int ra = (m0 + g) * PB + k0 + 2 * t;
            uint32_t ah0 = LD32(sXh, ra);
            uint32_t ah1 = LD32(sXh, ra + 8 * PB);
            uint32_t ah2 = LD32(sXh, ra + 8);
            uint32_t ah3 = LD32(sXh, ra + 8 * PB + 8);
            uint32_t al0 = LD32(sXl, ra);
            uint32_t al1 = LD32(sXl, ra + 8 * PB);
            uint32_t al2 = LD32(sXl, ra + 8);
            uint32_t al3 = LD32(sXl, ra + 8 * PB + 8);
            #pragma unroll
            for (int j = 0; j < 8; ++j) {
                int rb = (8 * j + g) * PB + k0 + 2 * t;
                uint32_t k0r = LD32(sWk, rb), k1r = LD32(sWk, rb + 8);
                mma_f16(accK[j], ah0, ah1, ah2, ah3, k0r, k1r);
                uint32_t vh0 = LD32(sWvh, rb), vh1 = LD32(sWvh, rb + 8);
                uint32_t vl0 = LD32(sWvl, rb), vl1 = LD32(sWvl, rb + 8);
                mma_f16(accV[j], ah0, ah1, ah2, ah3, vh0, vh1);
                mma_f16(accV[j], ah0, ah1, ah2, ah3, vl0, vl1);
                mma_f16(accV[j], al0, al1, al2, al3, vh0, vh1);
            }
        }
    }

    const int row0 = RB + m0 + g;
    const int batch = row0 / T_DIM;
    const int tl0 = row0 % T_DIM;

    #pragma unroll
    for (int j = 0; j < 8; ++j) {
        int col = 8 * j + 2 * t;
        *(uint32_t*)&g_kh[(size_t)row0 * HS + col] = hpack(accK[j][0], accK[j][1]);
        *(uint32_t*)&g_kh[(size_t)(row0 + 8) * HS + col] = hpack(accK[j][2], accK[j][3]);
        *(uint32_t*)&g_qh[(size_t)row0 * HS + col] = hpack(accV[j][0], accV[j][1]);
        *(uint32_t*)&g_qh[(size_t)(row0 + 8) * HS + col] = hpack(accV[j][2], accV[j][3]);
        #pragma unroll
        for (int q = 0; q < 4; ++q) {
            float v = accV[j][q];
            int cc = col + (q & 1);
            int tt = tl0 + (q >> 1) * 8;
            __half hv = __float2half_rn(v);
            __half lv = __float2half_rn(v - __half2float(hv));
            size_t off = ((size_t)batch * HS + cc) * T_DIM + tt;
            g_vth[off] = *(uint16_t*)&hv;
            g_vtl[off] = *(uint16_t*)&lv;
        }
    }
}

// ---------------------------------------------------------------------------
// Split-KV flash attention, QBLK=128, 3-stage cp.async pipeline.
// ---------------------------------------------------------------------------
#define ABYTES (64 * PB * 2)
#define BUFBYTES (3 * ABYTES)
#define AU16 (64 * PB)
#define NSTAGE 3

__global__ __launch_bounds__(128, 2) void attn_kernel() {
    const int mblk = 31 - blockIdx.x;          // longest-first
    const int kbLast = 2 * mblk + 1;
    const int kb0 = blockIdx.y * CBLK;
    if (kb0 > kbLast) return;
    const int kb1 = min(kb0 + CBLK - 1, kbLast);
    const int b = blockIdx.z;
    const int unit = (b * 32 + mblk) * NCHUNK + blockIdx.y;

    extern __shared__ __align__(16) uint16_t sm[];
    const uint32_t smb = (uint32_t)__cvta_generic_to_shared(sm);

    const int tid = threadIdx.x;
    const int w = tid >> 5, lane = tid & 31, g = lane >> 2, t = lane & 3;
    const int qRow = mblk * QBLK;
    const int m0 = w * 32;
    const int lr = tid >> 3;
    const int lc = (tid & 7) * 8;

    // Q A-fragments (single fp16), two row tiles
    uint32_t q[2][4][4];
    {
        const uint16_t* Qh = g_qh + (size_t)b * T_DIM * HS;
        #pragma unroll
        for (int tt = 0; tt < 2; ++tt) {
            int base = (qRow + m0 + tt * 16 + g) * HS + 2 * t;
            #pragma unroll
            for (int kk = 0; kk < 4; ++kk) {
                int o = base + kk * 16;
                q[tt][kk][0] = LD32(Qh, o);
                q[tt][kk][1] = LD32(Qh, o + 8 * HS);
                q[tt][kk][2] = LD32(Qh, o + 8);
                q[tt][kk][3] = LD32(Qh, o + 8 * HS + 8);
            }
        }
    }

    auto issue_tile = [&](int kb) {
        uint32_t base = smb + (uint32_t)(kb % NSTAGE) * BUFBYTES;
        #pragma unroll
        for (int l = 0; l < 4; ++l) {
            int r = lr + l * 16;
            uint32_t soff = (uint32_t)(r * PB + lc) * 2;
            size_t gk = ((size_t)b * T_DIM + kb * 64 + r) * HS + lc;
            cpa16(base + soff, &g_kh[gk]);
            size_t gv = ((size_t)b * HS + r) * T_DIM + kb * 64 + lc;
            cpa16(base + ABYTES + soff, &g_vth[gv]);
            cpa16(base + 2 * ABYTES + soff, &g_vtl[gv]);
        }
        asm volatile("cp.async.commit_group;");
    };

    issue_tile(kb0);
    if (kb0 + 1 <= kb1) issue_tile(kb0 + 1);

    float acc[2][8][4] = {};
    float mrow[4] = {-1e30f, -1e30f, -1e30f, -1e30f};
    float lrow[4] = {0.f, 0.f, 0.f, 0.f};

    for (int kb = kb0; kb <= kb1; ++kb) {
        if (kb < kb1) {
            asm volatile("cp.async.wait_group 1;" ::: "memory");
        } else {
            asm volatile("cp.async.wait_group 0;" ::: "memory");
        }
        __syncthreads();
        if (kb + 2 <= kb1) issue_tile(kb + 2);

        const uint16_t* bKh = sm + (kb % NSTAGE) * 3 * AU16;
        const uint16_t* bVh = bKh + AU16;
        const uint16_t* bVl = bKh + 2 * AU16;

        // S = Q @ K^T for both row tiles
        float s[2][8][4] = {};
        #pragma unroll
        for (int kk = 0; kk < 4; ++kk) {
            #pragma unroll
            for (int j = 0; j < 8; ++j) {
                int rb = (8 * j + g) * PB + kk * 16 + 2 * t;
                uint32_t b0 = LD32(bKh, rb), b1 = LD32(bKh, rb + 8);
                mma_f16(s[0][j], q[0][kk][0], q[0][kk][1], q[0][kk][2], q[0][kk][3], b0, b1);
                mma_f16(s[1][j], q[1][kk][0], q[1][kk][1], q[1][kk][2], q[1][kk][3], b0, b1);
            }
        }

        // causal mask: only last two kv blocks overlap the diagonal
        if (kb >= 2 * mblk) {
            const int off = qRow - kb * 64;
            #pragma unroll
            for (int tt = 0; tt < 2; ++tt) {
                int r0l = m0 + tt * 16 + g + off, r1l = r0l + 8;
                #pragma unroll
                for (int j = 0; j < 8; ++j) {
                    int c0 = 8 * j + 2 * t, c1 = c0 + 1;
                    if (c0 > r0l) s[tt][j][0] = -1e30f;
                    if (c1 > r0l) s[tt][j][1] = -1e30f;
                    if (c0 > r1l) s[tt][j][2] = -1e30f;
                    if (c1 > r1l) s[tt][j][3] = -1e30f;
                }
            }
        }

        #pragma unroll
        for (int tt = 0; tt < 2; ++tt) {
            float mx0 = -1e30f, mx1 = -1e30f;
            #pragma unroll
            for (int j = 0; j < 8; ++j) {
                mx0 = fmaxf(mx0, fmaxf(s[tt][j][0], s[tt][j][1]));
                mx1 = fmaxf(mx1, fmaxf(s[tt][j][2], s[tt][j][3]));
            }
            mx0 = fmaxf(mx0, __shfl_xor_sync(0xffffffffu, mx0, 1));
            mx0 = fmaxf(mx0, __shfl_xor_sync(0xffffffffu, mx0, 2));
            mx1 = fmaxf(mx1, __shfl_xor_sync(0xffffffffu, mx1, 1));
            mx1 = fmaxf(mx1, __shfl_xor_sync(0xffffffffu, mx1, 2));
            float mn0 = fmaxf(mrow[tt * 2], mx0), mn1 = fmaxf(mrow[tt * 2 + 1], mx1);
            float cr0 = exp2f((mrow[tt * 2] - mn0) * CSC);
            float cr1 = exp2f((mrow[tt * 2 + 1] - mn1) * CSC);
            float sum0 = 0.f, sum1 = 0.f;
            #pragma unroll
            for (int j = 0; j < 8; ++j) {
                s[tt][j][0] = exp2f((s[tt][j][0] - mn0) * CSC);
                s[tt][j][1] = exp2f((s[tt][j][1] - mn0) * CSC);
                s[tt][j][2] = exp2f((s[tt][j][2] - mn1) * CSC);
                s[tt][j][3] = exp2f((s[tt][j][3] - mn1) * CSC);
                sum0 += s[tt][j][0] + s[tt][j][1];
                sum1 += s[tt][j][2] + s[tt][j][3];
            }
            sum0 += __shfl_xor_sync(0xffffffffu, sum0, 1);
            sum0 += __shfl_xor_sync(0xffffffffu, sum0, 2);
            sum1 += __shfl_xor_sync(0xffffffffu, sum1, 1);
            sum1 += __shfl_xor_sync(0xffffffffu, sum1, 2);
            lrow[tt * 2] = lrow[tt * 2] * cr0 + sum0;
            lrow[tt * 2 + 1] = lrow[tt * 2 + 1] * cr1 + sum1;
            mrow[tt * 2] = mn0;
            mrow[tt * 2 + 1] = mn1;
            #pragma unroll
            for (int j = 0; j < 8; ++j) {
                acc[tt][j][0] *= cr0;
                acc[tt][j][1] *= cr0;
                acc[tt][j][2] *= cr1;
                acc[tt][j][3] *= cr1;
            }
        }

        // P (hi only) x V hi/lo for both row tiles
        #pragma unroll
        for (int kk = 0; kk < 4; ++kk) {
            uint32_t ph[2][4];
            #pragma unroll
            for (int tt = 0; tt < 2; ++tt) {
                float* pA = s[tt][2 * kk];
                float* pB = s[tt][2 * kk + 1];
                ph[tt][0] = hpack(pA[0], pA[1]);
                ph[tt][1] = hpack(pA[2], pA[3]);
                ph[tt][2] = hpack(pB[0], pB[1]);
                ph[tt][3] = hpack(pB[2], pB[3]);
            }
            #pragma unroll
            for (int j = 0; j < 8; ++j) {
                int rb = (8 * j + g) * PB + kk * 16 + 2 * t;
                uint32_t vh0 = LD32(bVh, rb), vh1 = LD32(bVh, rb + 8);
                uint32_t vl0 = LD32(bVl, rb), vl1 = LD32(bVl, rb + 8);
                mma_f16(acc[0][j], ph[0][0], ph[0][1], ph[0][2], ph[0][3], vh0, vh1);
                mma_f16(acc[0][j], ph[0][0], ph[0][1], ph[0][2], ph[0][3], vl0, vl1);
                mma_f16(acc[1][j], ph[1][0], ph[1][1], ph[1][2], ph[1][3], vh0, vh1);
                mma_f16(acc[1][j], ph[1][0], ph[1][1], ph[1][2], ph[1][3], vl0, vl1);
            }
        }
    }

    // write partials (O as fp16)
    if (t == 0) {
        #pragma unroll
        for (int tt = 0; tt < 2; ++tt) {
            int r = m0 + tt * 16 + g;
            g_pm[(size_t)unit * QBLK + r] = mrow[tt * 2];
            g_pm[(size_t)unit * QBLK + r + 8] = mrow[tt * 2 + 1];
            g_pl[(size_t)unit * QBLK + r] = lrow[tt * 2];
            g_pl[(size_t)unit * QBLK + r + 8] = lrow[tt * 2 + 1];
        }
    }
    #pragma unroll
    for (int tt = 0; tt < 2; ++tt) {
        int r = m0 + tt * 16 + g;
        #pragma unroll
        for (int j = 0; j < 8; ++j) {
            int col = 8 * j + 2 * t;
            size_t pbase = ((size_t)unit * QBLK + r) * HS + col;
            *(uint32_t*)&g_po[pbase] = hpack(acc[tt][j][0], acc[tt][j][1]);
            *(uint32_t*)&g_po[pbase + 8 * HS] = hpack(acc[tt][j][2], acc[tt][j][3]);
        }
    }
}

// ---------------------------------------------------------------------------
// Combine fp16 partials. Grid (32, B, 8): blockIdx.z = 8-col octet.
// ---------------------------------------------------------------------------
__global__ __launch_bounds__(256) void reduce_kernel(float* __restrict__ out) {
    const int mb = blockIdx.x, b = blockIdx.y;
    const int nc = (2 * mb + 2 + CBLK - 1) / CBLK;
    const int tid = threadIdx.x;
    const int r = tid >> 1;
    const int col = blockIdx.z * 8 + (tid & 1) * 4;
    const size_t ubase = ((size_t)(b * 32 + mb)) * NCHUNK;

    float m[NCHUNK], wgt[NCHUNK];
    float mstar = -1e30f;
    #pragma unroll
    for (int c = 0; c < NCHUNK; ++c) {
        if (c < nc) {
            m[c] = g_pm[(ubase + c) * QBLK + r];
            mstar = fmaxf(mstar, m[c]);
        }
    }
    float lsum = 0.f;
    #pragma unroll
    for (int c = 0; c < NCHUNK; ++c) {
        if (c < nc) {
            wgt[c] = exp2f((m[c] - mstar) * CSC);
            lsum += wgt[c] * g_pl[(ubase + c) * QBLK + r];
        }
    }
    float inv = 1.f / lsum;

    float4 o = make_float4(0.f, 0.f, 0.f, 0.f);
    #pragma unroll
    for (int c = 0; c < NCHUNK; ++c) {
        if (c < nc) {
            uint2 pk = *(const uint2*)&g_po[((ubase + c) * QBLK + r) * HS + col];
            float2 p01 = __half22float2(*(__half2*)&pk.x);
            float2 p23 = __half22float2(*(__half2*)&pk.y);
            o.x += wgt[c] * p01.x;
            o.y += wgt[c] * p01.y;
            o.z += wgt[c] * p23.x;
            o.w += wgt[c] * p23.y;
        }
    }
    *(float4*)&out[((size_t)b * T_DIM + mb * QBLK + r) * HS + col] =
        make_float4(o.x * inv, o.y * inv, o.z * inv, o.w * inv);
}

extern "C" void kernel_launch(void* const* d_in, const int* in_sizes, int n_in,
                              void* d_out, int out_size) {
    const float* x = (const float*)d_in[0];
    const float* Wk = (const float*)d_in[1];
    const float* Wv = (const float*)d_in[2];
    float* out = (float*)d_out;

    const int smemProj = 5 * 64 * PB * sizeof(uint16_t);  // 46080
    const int smemAttn = NSTAGE * BUFBYTES;               // 82944
    cudaFuncSetAttribute(proj_kernel, cudaFuncAttributeMaxDynamicSharedMemorySize, smemProj);
    cudaFuncSetAttribute(attn_kernel, cudaFuncAttributeMaxDynamicSharedMemorySize, smemAttn);

    wconv_kernel<<<HS * D_DIM / 512, 256>>>(Wk, Wv);
    proj_kernel<<<(B_DIM * T_DIM) / 64, 128, smemProj>>>(x);
    attn_kernel<<<dim3(32, NCHUNK, B_DIM), 128, smemAttn>>>();
    reduce_kernel<<<dim3(32, B_DIM, 8), 256>>>(out);
}

// round 11
// speedup vs baseline: 1.2309x; 1.1185x over previous
#include <cuda_runtime.h>
#include <cuda_fp16.h>
#include <cstdint>

#define B_DIM 4
#define T_DIM 4096
#define D_DIM 1024
#define HS 64
#define PB 72      // fp16 pitch: conflict-free frag loads, 16B-aligned rows
#define QBLK 128   // q rows per attn CTA
#define NCHUNK 8   // max kv chunks per q-block
#define CBLK 8     // kv blocks (of 64 keys) per chunk

// Projected tensors (fp16, single precision level)
__device__ __align__(16) uint16_t g_kh[B_DIM * T_DIM * HS];
__device__ __align__(16) uint16_t g_qh[B_DIM * T_DIM * HS];
__device__ __align__(16) uint16_t g_vth[B_DIM * HS * T_DIM];  // QV^T [b][h][t]

// Preconverted weights: Wk hi; Wv hi/lo (lo still used for accurate projection)
__device__ __align__(16) uint16_t g_wkh[HS * D_DIM];
__device__ __align__(16) uint16_t g_wvh[HS * D_DIM];
__device__ __align__(16) uint16_t g_wvl[HS * D_DIM];

// Split-KV partials: unit = (b*32 + mblk)*NCHUNK + chunk, 128 rows each
__device__ __align__(16) uint16_t g_po[B_DIM * 32 * NCHUNK * QBLK * HS];  // fp16
__device__ float g_pm[B_DIM * 32 * NCHUNK * QBLK];
__device__ float g_pl[B_DIM * 32 * NCHUNK * QBLK];

#define CSC 0.1803368801111204f  // 0.125 * log2(e)

__device__ __forceinline__ uint32_t hpack(float a, float b) {
    __half2 hh = __floats2half2_rn(a, b);
    return *(uint32_t*)&hh;
}
__device__ __forceinline__ void packpair(float a, float b, uint32_t& h, uint32_t& l) {
    __half2 hh = __floats2half2_rn(a, b);
    h = *(uint32_t*)&hh;
    float2 fb = __half22float2(hh);
    l = hpack(a - fb.x, b - fb.y);
}
__device__ __forceinline__ void mma_f16(float* c, uint32_t a0, uint32_t a1,
                                        uint32_t a2, uint32_t a3,
                                        uint32_t b0, uint32_t b1) {
    asm volatile(
        "mma.sync.aligned.m16n8k16.row.col.f32.f16.f16.f32 "
        "{%0,%1,%2,%3}, {%4,%5,%6,%7}, {%8,%9}, {%0,%1,%2,%3};"
        : "+f"(c[0]), "+f"(c[1]), "+f"(c[2]), "+f"(c[3])
        : "r"(a0), "r"(a1), "r"(a2), "r"(a3), "r"(b0), "r"(b1));
}
__device__ __forceinline__ void sstore2(uint16_t* Sh, uint16_t* Sl, int off,
                                        float a, float b) {
    uint32_t h, l;
    packpair(a, b, h, l);
    *(uint32_t*)&Sh[off] = h;
    *(uint32_t*)&Sl[off] = l;
}
__device__ __forceinline__ void cpa16(uint32_t dst, const void* src) {
    asm volatile("cp.async.cg.shared.global [%0], [%1], 16;" :: "r"(dst), "l"(src));
}
#define LD32(arr, idx) (*(const uint32_t*)&(arr)[idx])

// ---------------------------------------------------------------------------
// One-time weight conversion fp32 -> fp16 (Wk hi; Wv hi/lo)
// ---------------------------------------------------------------------------
__global__ __launch_bounds__(256) void wconv_kernel(const float* __restrict__ Wk,
                                                    const float* __restrict__ Wv) {
    int i = blockIdx.x * 512 + threadIdx.x * 2;
    *(uint32_t*)&g_wkh[i] = hpack(Wk[i], Wk[i + 1]);
    uint32_t h, l;
    packpair(Wv[i], Wv[i + 1], h, l);
    *(uint32_t*)&g_wvh[i] = h;
    *(uint32_t*)&g_wvl[i] = l;
}

// ---------------------------------------------------------------------------
// Projection: 64-row CTAs, 128 thr, 3 CTAs/SM.
// k = x@Wk^T (1-MMA), qv = x@Wv^T (3-MMA). W via cp.async.
// ---------------------------------------------------------------------------
__global__ __launch_bounds__(128, 3) void proj_kernel(const float* __restrict__ x) {
    extern __shared__ __align__(16) uint16_t sm[];
    uint16_t* sXh = sm;
    uint16_t* sXl = sXh + 64 * PB;
    uint16_t* sWk = sXl + 64 * PB;
    uint16_t* sWvh = sWk + 64 * PB;
    uint16_t* sWvl = sWvh + 64 * PB;
    const uint32_t smb = (uint32_t)__cvta_generic_to_shared(sm);
    const uint32_t AB = 64 * PB * 2;

    const int tid = threadIdx.x;
    const int w = tid >> 5, lane = tid & 31, g = lane >> 2, t = lane & 3;
    const int RB = blockIdx.x * 64;
    const int m0 = w * 16;

    float accK[8][4] = {};
    float accV[8][4] = {};

    for (int d0 = 0; d0 < D_DIM; d0 += 64) {
        __syncthreads();
        #pragma unroll
        for (int l = 0; l < 4; ++l) {
            int id = tid + l * 128;
            int r = id >> 3, c8 = (id & 7) * 8;
            uint32_t soff = (uint32_t)(r * PB + c8) * 2;
            size_t go = (size_t)r * D_DIM + d0 + c8;
            cpa16(smb + 2 * AB + soff, &g_wkh[go]);
            cpa16(smb + 3 * AB + soff, &g_wvh[go]);
            cpa16(smb + 4 * AB + soff, &g_wvl[go]);
        }
        asm volatile("cp.async.commit_group;");
        #pragma unroll
        for (int l = 0; l < 8; ++l) {
            int idx = tid + l * 128;
            int r = idx >> 4, c = (idx & 15) * 4;
            float4 fx = *(const float4*)&x[(size_t)(RB + r) * D_DIM + d0 + c];
            sstore2(sXh, sXl, r * PB + c, fx.x, fx.y);
            sstore2(sXh, sXl, r * PB + c + 2, fx.z, fx.w);
        }
        asm volatile("cp.async.wait_group 0;" ::: "memory");
        __syncthreads();

        #pragma unroll
        for (int k0 = 0; k0 < 64; k0 += 16) {
            int ra = (m0 + g) * PB + k0 + 2 * t;
            uint32_t ah0 = LD32(sXh, ra);
            uint32_t ah1 = LD32(sXh, ra + 8 * PB);
            uint32_t ah2 = LD32(sXh, ra + 8);
            uint32_t ah3 = LD32(sXh, ra + 8 * PB + 8);
            uint32_t al0 = LD32(sXl, ra);
            uint32_t al1 = LD32(sXl, ra + 8 * PB);
            uint32_t al2 = LD32(sXl, ra + 8);
            uint32_t al3 = LD32(sXl, ra + 8 * PB + 8);
            #pragma unroll
            for (int j = 0; j < 8; ++j) {
                int rb = (8 * j + g) * PB + k0 + 2 * t;
                uint32_t k0r = LD32(sWk, rb), k1r = LD32(sWk, rb + 8);
                mma_f16(accK[j], ah0, ah1, ah2, ah3, k0r, k1r);
                uint32_t vh0 = LD32(sWvh, rb), vh1 = LD32(sWvh, rb + 8);
                uint32_t vl0 = LD32(sWvl, rb), vl1 = LD32(sWvl, rb + 8);
                mma_f16(accV[j], ah0, ah1, ah2, ah3, vh0, vh1);
                mma_f16(accV[j], ah0, ah1, ah2, ah3, vl0, vl1);
                mma_f16(accV[j], al0, al1, al2, al3, vh0, vh1);
            }
        }
    }

    const int row0 = RB + m0 + g;
    const int batch = row0 / T_DIM;
    const int tl0 = row0 % T_DIM;

    #pragma unroll
    for (int j = 0; j < 8; ++j) {
        int col = 8 * j + 2 * t;
        *(uint32_t*)&g_kh[(size_t)row0 * HS + col] = hpack(accK[j][0], accK[j][1]);
        *(uint32_t*)&g_kh[(size_t)(row0 + 8) * HS + col] = hpack(accK[j][2], accK[j][3]);
        *(uint32_t*)&g_qh[(size_t)row0 * HS + col] = hpack(accV[j][0], accV[j][1]);
        *(uint32_t*)&g_qh[(size_t)(row0 + 8) * HS + col] = hpack(accV[j][2], accV[j][3]);
        #pragma unroll
        for (int q = 0; q < 4; ++q) {
            float v = accV[j][q];
            int cc = col + (q & 1);
            int tt = tl0 + (q >> 1) * 8;
            __half hv = __float2half_rn(v);
            g_vth[((size_t)batch * HS + cc) * T_DIM + tt] = *(uint16_t*)&hv;
        }
    }
}

// ---------------------------------------------------------------------------
// Split-KV flash attention, QBLK=128, V single fp16, 3-stage pipeline.
// ---------------------------------------------------------------------------
#define ABYTES (64 * PB * 2)
#define BUFBYTES (2 * ABYTES)   // Kh, Vth
#define AU16 (64 * PB)
#define NSTAGE 3

__global__ __launch_bounds__(128, 2) void attn_kernel() {
    const int mblk = 31 - blockIdx.x;          // longest-first
    const int kbLast = 2 * mblk + 1;
    const int kb0 = blockIdx.y * CBLK;
    if (kb0 > kbLast) return;
    const int kb1 = min(kb0 + CBLK - 1, kbLast);
    const int b = blockIdx.z;
    const int unit = (b * 32 + mblk) * NCHUNK + blockIdx.y;

    extern __shared__ __align__(16) uint16_t sm[];
    const uint32_t smb = (uint32_t)__cvta_generic_to_shared(sm);

    const int tid = threadIdx.x;
    const int w = tid >> 5, lane = tid & 31, g = lane >> 2, t = lane & 3;
    const int qRow = mblk * QBLK;
    const int m0 = w * 32;
    const int lr = tid >> 3;
    const int lc = (tid & 7) * 8;

    // Q A-fragments (single fp16), two row tiles
    uint32_t q[2][4][4];
    {
        const uint16_t* Qh = g_qh + (size_t)b * T_DIM * HS;
        #pragma unroll
        for (int tt = 0; tt < 2; ++tt) {
            int base = (qRow + m0 + tt * 16 + g) * HS + 2 * t;
            #pragma unroll
            for (int kk = 0; kk < 4; ++kk) {
                int o = base + kk * 16;
                q[tt][kk][0] = LD32(Qh, o);
                q[tt][kk][1] = LD32(Qh, o + 8 * HS);
                q[tt][kk][2] = LD32(Qh, o + 8);
                q[tt][kk][3] = LD32(Qh, o + 8 * HS + 8);
            }
        }
    }

    auto issue_tile = [&](int kb) {
        uint32_t base = smb + (uint32_t)(kb % NSTAGE) * BUFBYTES;
        #pragma unroll
        for (int l = 0; l < 4; ++l) {
            int r = lr + l * 16;
            uint32_t soff = (uint32_t)(r * PB + lc) * 2;
            size_t gk = ((size_t)b * T_DIM + kb * 64 + r) * HS + lc;
            cpa16(base + soff, &g_kh[gk]);
            size_t gv = ((size_t)b * HS + r) * T_DIM + kb * 64 + lc;
            cpa16(base + ABYTES + soff, &g_vth[gv]);
        }
        asm volatile("cp.async.commit_group;");
    };

    issue_tile(kb0);
    if (kb0 + 1 <= kb1) issue_tile(kb0 + 1);

    float acc[2][8][4] = {};
    float mrow[4] = {-1e30f, -1e30f, -1e30f, -1e30f};
    float lrow[4] = {0.f, 0.f, 0.f, 0.f};

    for (int kb = kb0; kb <= kb1; ++kb) {
        if (kb < kb1) {
            asm volatile("cp.async.wait_group 1;" ::: "memory");
        } else {
            asm volatile("cp.async.wait_group 0;" ::: "memory");
        }
        __syncthreads();
        if (kb + 2 <= kb1) issue_tile(kb + 2);

        const uint16_t* bKh = sm + (kb % NSTAGE) * 2 * AU16;
        const uint16_t* bVh = bKh + AU16;

        // S = Q @ K^T for both row tiles
        float s[2][8][4] = {};
        #pragma unroll
        for (int kk = 0; kk < 4; ++kk) {
            #pragma unroll
            for (int j = 0; j < 8; ++j) {
                int rb = (8 * j + g) * PB + kk * 16 + 2 * t;
                uint32_t b0 = LD32(bKh, rb), b1 = LD32(bKh, rb + 8);
                mma_f16(s[0][j], q[0][kk][0], q[0][kk][1], q[0][kk][2], q[0][kk][3], b0, b1);
                mma_f16(s[1][j], q[1][kk][0], q[1][kk][1], q[1][kk][2], q[1][kk][3], b0, b1);
            }
        }

        // causal mask: only last two kv blocks overlap the diagonal
        if (kb >= 2 * mblk) {
            const int off = qRow - kb * 64;
            #pragma unroll
            for (int tt = 0; tt < 2; ++tt) {
                int r0l = m0 + tt * 16 + g + off, r1l = r0l + 8;
                #pragma unroll
                for (int j = 0; j < 8; ++j) {
                    int c0 = 8 * j + 2 * t, c1 = c0 + 1;
                    if (c0 > r0l) s[tt][j][0] = -1e30f;
                    if (c1 > r0l) s[tt][j][1] = -1e30f;
                    if (c0 > r1l) s[tt][j][2] = -1e30f;
                    if (c1 > r1l) s[tt][j][3] = -1e30f;
                }
            }
        }

        #pragma unroll
        for (int tt = 0; tt < 2; ++tt) {
            float mx0 = -1e30f, mx1 = -1e30f;
            #pragma unroll
            for (int j = 0; j < 8; ++j) {
                mx0 = fmaxf(mx0, fmaxf(s[tt][j][0], s[tt][j][1]));
                mx1 = fmaxf(mx1, fmaxf(s[tt][j][2], s[tt][j][3]));
            }
            mx0 = fmaxf(mx0, __shfl_xor_sync(0xffffffffu, mx0, 1));
            mx0 = fmaxf(mx0, __shfl_xor_sync(0xffffffffu, mx0, 2));
            mx1 = fmaxf(mx1, __shfl_xor_sync(0xffffffffu, mx1, 1));
            mx1 = fmaxf(mx1, __shfl_xor_sync(0xffffffffu, mx1, 2));
            float mn0 = fmaxf(mrow[tt * 2], mx0), mn1 = fmaxf(mrow[tt * 2 + 1], mx1);
            float cr0 = exp2f((mrow[tt * 2] - mn0) * CSC);
            float cr1 = exp2f((mrow[tt * 2 + 1] - mn1) * CSC);
            float sum0 = 0.f, sum1 = 0.f;
            #pragma unroll
            for (int j = 0; j < 8; ++j) {
                s[tt][j][0] = exp2f((s[tt][j][0] - mn0) * CSC);
                s[tt][j][1] = exp2f((s[tt][j][1] - mn0) * CSC);
                s[tt][j][2] = exp2f((s[tt][j][2] - mn1) * CSC);
                s[tt][j][3] = exp2f((s[tt][j][3] - mn1) * CSC);
                sum0 += s[tt][j][0] + s[tt][j][1];
                sum1 += s[tt][j][2] + s[tt][j][3];
            }
            sum0 += __shfl_xor_sync(0xffffffffu, sum0, 1);
            sum0 += __shfl_xor_sync(0xffffffffu, sum0, 2);
            sum1 += __shfl_xor_sync(0xffffffffu, sum1, 1);
            sum1 += __shfl_xor_sync(0xffffffffu, sum1, 2);
            lrow[tt * 2] = lrow[tt * 2] * cr0 + sum0;
            lrow[tt * 2 + 1] = lrow[tt * 2 + 1] * cr1 + sum1;
            mrow[tt * 2] = mn0;
            mrow[tt * 2 + 1] = mn1;
            #pragma unroll
            for (int j = 0; j < 8; ++j) {
                acc[tt][j][0] *= cr0;
                acc[tt][j][1] *= cr0;
                acc[tt][j][2] *= cr1;
                acc[tt][j][3] *= cr1;
            }
        }

        // P (hi) x V (single fp16)
        #pragma unroll
        for (int kk = 0; kk < 4; ++kk) {
            uint32_t ph[2][4];
            #pragma unroll
            for (int tt = 0; tt < 2; ++tt) {
                float* pA = s[tt][2 * kk];
                float* pB = s[tt][2 * kk + 1];
                ph[tt][0] = hpack(pA[0], pA[1]);
                ph[tt][1] = hpack(pA[2], pA[3]);
                ph[tt][2] = hpack(pB[0], pB[1]);
                ph[tt][3] = hpack(pB[2], pB[3]);
            }
            #pragma unroll
            for (int j = 0; j < 8; ++j) {
                int rb = (8 * j + g) * PB + kk * 16 + 2 * t;
                uint32_t vh0 = LD32(bVh, rb), vh1 = LD32(bVh, rb + 8);
                mma_f16(acc[0][j], ph[0][0], ph[0][1], ph[0][2], ph[0][3], vh0, vh1);
                mma_f16(acc[1][j], ph[1][0], ph[1][1], ph[1][2], ph[1][3], vh0, vh1);
            }
        }
    }

    // write partials (O as fp16)
    if (t == 0) {
        #pragma unroll
        for (int tt = 0; tt < 2; ++tt) {
            int r = m0 + tt * 16 + g;
            g_pm[(size_t)unit * QBLK + r] = mrow[tt * 2];
            g_pm[(size_t)unit * QBLK + r + 8] = mrow[tt * 2 + 1];
            g_pl[(size_t)unit * QBLK + r] = lrow[tt * 2];
            g_pl[(size_t)unit * QBLK + r + 8] = lrow[tt * 2 + 1];
        }
    }
    #pragma unroll
    for (int tt = 0; tt < 2; ++tt) {
        int r = m0 + tt * 16 + g;
        #pragma unroll
        for (int j = 0; j < 8; ++j) {
            int col = 8 * j + 2 * t;
            size_t pbase = ((size_t)unit * QBLK + r) * HS + col;
            *(uint32_t*)&g_po[pbase] = hpack(acc[tt][j][0], acc[tt][j][1]);
            *(uint32_t*)&g_po[pbase + 8 * HS] = hpack(acc[tt][j][2], acc[tt][j][3]);
        }
    }
}

// ---------------------------------------------------------------------------
// Combine fp16 partials. Grid (32, B, 8): blockIdx.z = 8-col octet.
// ---------------------------------------------------------------------------
__global__ __launch_bounds__(256) void reduce_kernel(float* __restrict__ out) {
    const int mb = blockIdx.x, b = blockIdx.y;
    const int nc = (2 * mb + 2 + CBLK - 1) / CBLK;
    const int tid = threadIdx.x;
    const int r = tid >> 1;
    const int col = blockIdx.z * 8 + (tid & 1) * 4;
    const size_t ubase = ((size_t)(b * 32 + mb)) * NCHUNK;

    float m[NCHUNK], wgt[NCHUNK];
    float mstar = -1e30f;
    #pragma unroll
    for (int c = 0; c < NCHUNK; ++c) {
        if (c < nc) {
            m[c] = g_pm[(ubase + c) * QBLK + r];
            mstar = fmaxf(mstar, m[c]);
        }
    }
    float lsum = 0.f;
    #pragma unroll
    for (int c = 0; c < NCHUNK; ++c) {
        if (c < nc) {
            wgt[c] = exp2f((m[c] - mstar) * CSC);
            lsum += wgt[c] * g_pl[(ubase + c) * QBLK + r];
        }
    }
    float inv = 1.f / lsum;

    float4 o = make_float4(0.f, 0.f, 0.f, 0.f);
    #pragma unroll
    for (int c = 0; c < NCHUNK; ++c) {
        if (c < nc) {
            uint2 pk = *(const uint2*)&g_po[((ubase + c) * QBLK + r) * HS + col];
            float2 p01 = __half22float2(*(__half2*)&pk.x);
            float2 p23 = __half22float2(*(__half2*)&pk.y);
            o.x += wgt[c] * p01.x;
            o.y += wgt[c] * p01.y;
            o.z += wgt[c] * p23.x;
            o.w += wgt[c] * p23.y;
        }
    }
    *(float4*)&out[((size_t)b * T_DIM + mb * QBLK + r) * HS + col] =
        make_float4(o.x * inv, o.y * inv, o.z * inv, o.w * inv);
}

extern "C" void kernel_launch(void* const* d_in, const int* in_sizes, int n_in,
                              void* d_out, int out_size) {
    const float* x = (const float*)d_in[0];
    const float* Wk = (const float*)d_in[1];
    const float* Wv = (const float*)d_in[2];
    float* out = (float*)d_out;

    const int smemProj = 5 * 64 * PB * sizeof(uint16_t);  // 46080
    const int smemAttn = NSTAGE * BUFBYTES;               // 55296
    cudaFuncSetAttribute(proj_kernel, cudaFuncAttributeMaxDynamicSharedMemorySize, smemProj);
    cudaFuncSetAttribute(attn_kernel, cudaFuncAttributeMaxDynamicSharedMemorySize, smemAttn);

    wconv_kernel<<<HS * D_DIM / 512, 256>>>(Wk, Wv);
    proj_kernel<<<(B_DIM * T_DIM) / 64, 128, smemProj>>>(x);
    attn_kernel<<<dim3(32, NCHUNK, B_DIM), 128, smemAttn>>>();
    reduce_kernel<<<dim3(32, B_DIM, 8), 256>>>(out);
}

// round 12
// speedup vs baseline: 1.2959x; 1.0529x over previous
#include <cuda_runtime.h>
#include <cuda_fp16.h>
#include <cstdint>

#define B_DIM 4
#define T_DIM 4096
#define D_DIM 1024
#define HS 64
#define PB 72      // fp16 pitch: conflict-free frag loads, 16B-aligned rows
#define QBLK 128   // q rows per attn CTA
#define NCHUNK 8   // max kv chunks per q-block
#define CBLK 8     // kv blocks (of 64 keys) per chunk

// Projected tensors (fp16, single precision level)
__device__ __align__(16) uint16_t g_kh[B_DIM * T_DIM * HS];
__device__ __align__(16) uint16_t g_qh[B_DIM * T_DIM * HS];
__device__ __align__(16) uint16_t g_vth[B_DIM * HS * T_DIM];  // QV^T [b][h][t]

// Preconverted weights: Wk hi; Wv hi/lo
__device__ __align__(16) uint16_t g_wkh[HS * D_DIM];
__device__ __align__(16) uint16_t g_wvh[HS * D_DIM];
__device__ __align__(16) uint16_t g_wvl[HS * D_DIM];

// Split-KV partials: unit = (b*32 + mblk)*NCHUNK + chunk, 128 rows each
__device__ __align__(16) uint16_t g_po[B_DIM * 32 * NCHUNK * QBLK * HS];  // fp16
__device__ float g_pm[B_DIM * 32 * NCHUNK * QBLK];
__device__ float g_pl[B_DIM * 32 * NCHUNK * QBLK];

#define CSC 0.1803368801111204f  // 0.125 * log2(e)

__device__ __forceinline__ uint32_t hpack(float a, float b) {
    __half2 hh = __floats2half2_rn(a, b);
    return *(uint32_t*)&hh;
}
__device__ __forceinline__ void packpair(float a, float b, uint32_t& h, uint32_t& l) {
    __half2 hh = __floats2half2_rn(a, b);
    h = *(uint32_t*)&hh;
    float2 fb = __half22float2(hh);
    l = hpack(a - fb.x, b - fb.y);
}
__device__ __forceinline__ void mma_f16(float* c, uint32_t a0, uint32_t a1,
                                        uint32_t a2, uint32_t a3,
                                        uint32_t b0, uint32_t b1) {
    asm volatile(
        "mma.sync.aligned.m16n8k16.row.col.f32.f16.f16.f32 "
        "{%0,%1,%2,%3}, {%4,%5,%6,%7}, {%8,%9}, {%0,%1,%2,%3};"
        : "+f"(c[0]), "+f"(c[1]), "+f"(c[2]), "+f"(c[3])
        : "r"(a0), "r"(a1), "r"(a2), "r"(a3), "r"(b0), "r"(b1));
}
__device__ __forceinline__ void cpa16(uint32_t dst, const void* src) {
    asm volatile("cp.async.cg.shared.global [%0], [%1], 16;" :: "r"(dst), "l"(src));
}
#define LD32(arr, idx) (*(const uint32_t*)&(arr)[idx])

// ---------------------------------------------------------------------------
// One-time weight conversion fp32 -> fp16 (Wk hi; Wv hi/lo)
// ---------------------------------------------------------------------------
__global__ __launch_bounds__(256) void wconv_kernel(const float* __restrict__ Wk,
                                                    const float* __restrict__ Wv) {
    int i = blockIdx.x * 512 + threadIdx.x * 2;
    *(uint32_t*)&g_wkh[i] = hpack(Wk[i], Wk[i + 1]);
    uint32_t h, l;
    packpair(Wv[i], Wv[i + 1], h, l);
    *(uint32_t*)&g_wvh[i] = h;
    *(uint32_t*)&g_wvl[i] = l;
}

// ---------------------------------------------------------------------------
// Projection: 64-row CTAs, 128 thr, 3 CTAs/SM.
// k = xh@Wkh^T (1-MMA), qv = xh@(Wvh+Wvl)^T (2-MMA). W via cp.async.
// ---------------------------------------------------------------------------
__global__ __launch_bounds__(128, 3) void proj_kernel(const float* __restrict__ x) {
    extern __shared__ __align__(16) uint16_t sm[];
    uint16_t* sXh = sm;
    uint16_t* sWk = sXh + 64 * PB;
    uint16_t* sWvh = sWk + 64 * PB;
    uint16_t* sWvl = sWvh + 64 * PB;
    const uint32_t smb = (uint32_t)__cvta_generic_to_shared(sm);
    const uint32_t AB = 64 * PB * 2;

    const int tid = threadIdx.x;
    const int w = tid >> 5, lane = tid & 31, g = lane >> 2, t = lane & 3;
    const int RB = blockIdx.x * 64;
    const int m0 = w * 16;

    float accK[8][4] = {};
    float accV[8][4] = {};

    for (int d0 = 0; d0 < D_DIM; d0 += 64) {
        __syncthreads();
        #pragma unroll
        for (int l = 0; l < 4; ++l) {
            int id = tid + l * 128;
            int r = id >> 3, c8 = (id & 7) * 8;
            uint32_t soff = (uint32_t)(r * PB + c8) * 2;
            size_t go = (size_t)r * D_DIM + d0 + c8;
            cpa16(smb + AB + soff, &g_wkh[go]);
            cpa16(smb + 2 * AB + soff, &g_wvh[go]);
            cpa16(smb + 3 * AB + soff, &g_wvl[go]);
        }
        asm volatile("cp.async.commit_group;");
        // x tile: fp32 -> fp16 (hi only)
        #pragma unroll
        for (int l = 0; l < 8; ++l) {
            int idx = tid + l * 128;
            int r = idx >> 4, c = (idx & 15) * 4;
            float4 fx = *(const float4*)&x[(size_t)(RB + r) * D_DIM + d0 + c];
            *(uint32_t*)&sXh[r * PB + c] = hpack(fx.x, fx.y);
            *(uint32_t*)&sXh[r * PB + c + 2] = hpack(fx.z, fx.w);
        }
        asm volatile("cp.async.wait_group 0;" ::: "memory");
        __syncthreads();

        #pragma unroll
        for (int k0 = 0; k0 < 64; k0 += 16) {
            int ra = (m0 + g) * PB + k0 + 2 * t;
            uint32_t ah0 = LD32(sXh, ra);
            uint32_t ah1 = LD32(sXh, ra + 8 * PB);
            uint32_t ah2 = LD32(sXh, ra + 8);
            uint32_t ah3 = LD32(sXh, ra + 8 * PB + 8);
            #pragma unroll
            for (int j = 0; j < 8; ++j) {
                int rb = (8 * j + g) * PB + k0 + 2 * t;
                uint32_t k0r = LD32(sWk, rb), k1r = LD32(sWk, rb + 8);
                mma_f16(accK[j], ah0, ah1, ah2, ah3, k0r, k1r);
                uint32_t vh0 = LD32(sWvh, rb), vh1 = LD32(sWvh, rb + 8);
                uint32_t vl0 = LD32(sWvl, rb), vl1 = LD32(sWvl, rb + 8);
                mma_f16(accV[j], ah0, ah1, ah2, ah3, vh0, vh1);
                mma_f16(accV[j], ah0, ah1, ah2, ah3, vl0, vl1);
            }
        }
    }

    const int row0 = RB + m0 + g;
    const int batch = row0 / T_DIM;
    const int tl0 = row0 % T_DIM;

    #pragma unroll
    for (int j = 0; j < 8; ++j) {
        int col = 8 * j + 2 * t;
        *(uint32_t*)&g_kh[(size_t)row0 * HS + col] = hpack(accK[j][0], accK[j][1]);
        *(uint32_t*)&g_kh[(size_t)(row0 + 8) * HS + col] = hpack(accK[j][2], accK[j][3]);
        *(uint32_t*)&g_qh[(size_t)row0 * HS + col] = hpack(accV[j][0], accV[j][1]);
        *(uint32_t*)&g_qh[(size_t)(row0 + 8) * HS + col] = hpack(accV[j][2], accV[j][3]);
        #pragma unroll
        for (int q = 0; q < 4; ++q) {
            float v = accV[j][q];
            int cc = col + (q & 1);
            int tt = tl0 + (q >> 1) * 8;
            __half hv = __float2half_rn(v);
            g_vth[((size_t)batch * HS + cc) * T_DIM + tt] = *(uint16_t*)&hv;
        }
    }
}

// ---------------------------------------------------------------------------
// Split-KV flash attention, QBLK=128, V single fp16, 3-stage pipeline.
// ---------------------------------------------------------------------------
#define ABYTES (64 * PB * 2)
#define BUFBYTES (2 * ABYTES)   // Kh, Vth
#define AU16 (64 * PB)
#define NSTAGE 3

__global__ __launch_bounds__(128, 2) void attn_kernel() {
    const int mblk = 31 - blockIdx.x;          // longest-first
    const int kbLast = 2 * mblk + 1;
    const int kb0 = blockIdx.y * CBLK;
    if (kb0 > kbLast) return;
    const int kb1 = min(kb0 + CBLK - 1, kbLast);
    const int b = blockIdx.z;
    const int unit = (b * 32 + mblk) * NCHUNK + blockIdx.y;

    extern __shared__ __align__(16) uint16_t sm[];
    const uint32_t smb = (uint32_t)__cvta_generic_to_shared(sm);

    const int tid = threadIdx.x;
    const int w = tid >> 5, lane = tid & 31, g = lane >> 2, t = lane & 3;
    const int qRow = mblk * QBLK;
    const int m0 = w * 32;
    const int lr = tid >> 3;
    const int lc = (tid & 7) * 8;

    // Q A-fragments (single fp16), two row tiles
    uint32_t q[2][4][4];
    {
        const uint16_t* Qh = g_qh + (size_t)b * T_DIM * HS;
        #pragma unroll
        for (int tt = 0; tt < 2; ++tt) {
            int base = (qRow + m0 + tt * 16 + g) * HS + 2 * t;
            #pragma unroll
            for (int kk = 0; kk < 4; ++kk) {
                int o = base + kk * 16;
                q[tt][kk][0] = LD32(Qh, o);
                q[tt][kk][1] = LD32(Qh, o + 8 * HS);
                q[tt][kk][2] = LD32(Qh, o + 8);
                q[tt][kk][3] = LD32(Qh, o + 8 * HS + 8);
            }
        }
    }

    auto issue_tile = [&](int kb) {
        uint32_t base = smb + (uint32_t)(kb % NSTAGE) * BUFBYTES;
        #pragma unroll
        for (int l = 0; l < 4; ++l) {
            int r = lr + l * 16;
            uint32_t soff = (uint32_t)(r * PB + lc) * 2;
            size_t gk = ((size_t)b * T_DIM + kb * 64 + r) * HS + lc;
            cpa16(base + soff, &g_kh[gk]);
            size_t gv = ((size_t)b * HS + r) * T_DIM + kb * 64 + lc;
            cpa16(base + ABYTES + soff, &g_vth[gv]);
        }
        asm volatile("cp.async.commit_group;");
    };

    issue_tile(kb0);
    if (kb0 + 1 <= kb1) issue_tile(kb0 + 1);

    float acc[2][8][4] = {};
    float mrow[4] = {-1e30f, -1e30f, -1e30f, -1e30f};
    float lrow[4] = {0.f, 0.f, 0.f, 0.f};

    for (int kb = kb0; kb <= kb1; ++kb) {
        if (kb < kb1) {
            asm volatile("cp.async.wait_group 1;" ::: "memory");
        } else {
            asm volatile("cp.async.wait_group 0;" ::: "memory");
        }
        __syncthreads();
        if (kb + 2 <= kb1) issue_tile(kb + 2);

        const uint16_t* bKh = sm + (kb % NSTAGE) * 2 * AU16;
        const uint16_t* bVh = bKh + AU16;

        // S = Q @ K^T for both row tiles
        float s[2][8][4] = {};
        #pragma unroll
        for (int kk = 0; kk < 4; ++kk) {
            #pragma unroll
            for (int j = 0; j < 8; ++j) {
                int rb = (8 * j + g) * PB + kk * 16 + 2 * t;
                uint32_t b0 = LD32(bKh, rb), b1 = LD32(bKh, rb + 8);
                mma_f16(s[0][j], q[0][kk][0], q[0][kk][1], q[0][kk][2], q[0][kk][3], b0, b1);
                mma_f16(s[1][j], q[1][kk][0], q[1][kk][1], q[1][kk][2], q[1][kk][3], b0, b1);
            }
        }

        // causal mask: only last two kv blocks overlap the diagonal
        if (kb >= 2 * mblk) {
            const int off = qRow - kb * 64;
            #pragma unroll
            for (int tt = 0; tt < 2; ++tt) {
                int r0l = m0 + tt * 16 + g + off, r1l = r0l + 8;
                #pragma unroll
                for (int j = 0; j < 8; ++j) {
                    int c0 = 8 * j + 2 * t, c1 = c0 + 1;
                    if (c0 > r0l) s[tt][j][0] = -1e30f;
                    if (c1 > r0l) s[tt][j][1] = -1e30f;
                    if (c0 > r1l) s[tt][j][2] = -1e30f;
                    if (c1 > r1l) s[tt][j][3] = -1e30f;
                }
            }
        }

        #pragma unroll
        for (int tt = 0; tt < 2; ++tt) {
            float mx0 = -1e30f, mx1 = -1e30f;
            #pragma unroll
            for (int j = 0; j < 8; ++j) {
                mx0 = fmaxf(mx0, fmaxf(s[tt][j][0], s[tt][j][1]));
                mx1 = fmaxf(mx1, fmaxf(s[tt][j][2], s[tt][j][3]));
            }
            mx0 = fmaxf(mx0, __shfl_xor_sync(0xffffffffu, mx0, 1));
            mx0 = fmaxf(mx0, __shfl_xor_sync(0xffffffffu, mx0, 2));
            mx1 = fmaxf(mx1, __shfl_xor_sync(0xffffffffu, mx1, 1));
            mx1 = fmaxf(mx1, __shfl_xor_sync(0xffffffffu, mx1, 2));
            float mn0 = fmaxf(mrow[tt * 2], mx0), mn1 = fmaxf(mrow[tt * 2 + 1], mx1);
            float cr0 = exp2f((mrow[tt * 2] - mn0) * CSC);
            float cr1 = exp2f((mrow[tt * 2 + 1] - mn1) * CSC);
            float sum0 = 0.f, sum1 = 0.f;
            #pragma unroll
            for (int j = 0; j < 8; ++j) {
                s[tt][j][0] = exp2f((s[tt][j][0] - mn0) * CSC);
                s[tt][j][1] = exp2f((s[tt][j][1] - mn0) * CSC);
                s[tt][j][2] = exp2f((s[tt][j][2] - mn1) * CSC);
                s[tt][j][3] = exp2f((s[tt][j][3] - mn1) * CSC);
                sum0 += s[tt][j][0] + s[tt][j][1];
                sum1 += s[tt][j][2] + s[tt][j][3];
            }
            sum0 += __shfl_xor_sync(0xffffffffu, sum0, 1);
            sum0 += __shfl_xor_sync(0xffffffffu, sum0, 2);
            sum1 += __shfl_xor_sync(0xffffffffu, sum1, 1);
            sum1 += __shfl_xor_sync(0xffffffffu, sum1, 2);
            lrow[tt * 2] = lrow[tt * 2] * cr0 + sum0;
            lrow[tt * 2 + 1] = lrow[tt * 2 + 1] * cr1 + sum1;
            mrow[tt * 2] = mn0;
            mrow[tt * 2 + 1] = mn1;
            #pragma unroll
            for (int j = 0; j < 8; ++j) {
                acc[tt][j][0] *= cr0;
                acc[tt][j][1] *= cr0;
                acc[tt][j][2] *= cr1;
                acc[tt][j][3] *= cr1;
            }
        }

        // P (hi) x V (single fp16)
        #pragma unroll
        for (int kk = 0; kk < 4; ++kk) {
            uint32_t ph[2][4];
            #pragma unroll
            for (int tt = 0; tt < 2; ++tt) {
                float* pA = s[tt][2 * kk];
                float* pB = s[tt][2 * kk + 1];
                ph[tt][0] = hpack(pA[0], pA[1]);
                ph[tt][1] = hpack(pA[2], pA[3]);
                ph[tt][2] = hpack(pB[0], pB[1]);
                ph[tt][3] = hpack(pB[2], pB[3]);
            }
            #pragma unroll
            for (int j = 0; j < 8; ++j) {
                int rb = (8 * j + g) * PB + kk * 16 + 2 * t;
                uint32_t vh0 = LD32(bVh, rb), vh1 = LD32(bVh, rb + 8);
                mma_f16(acc[0][j], ph[0][0], ph[0][1], ph[0][2], ph[0][3], vh0, vh1);
                mma_f16(acc[1][j], ph[1][0], ph[1][1], ph[1][2], ph[1][3], vh0, vh1);
            }
        }
    }

    // write partials (O as fp16)
    if (t == 0) {
        #pragma unroll
        for (int tt = 0; tt < 2; ++tt) {
            int r = m0 + tt * 16 + g;
            g_pm[(size_t)unit * QBLK + r] = mrow[tt * 2];
            g_pm[(size_t)unit * QBLK + r + 8] = mrow[tt * 2 + 1];
            g_pl[(size_t)unit * QBLK + r] = lrow[tt * 2];
            g_pl[(size_t)unit * QBLK + r + 8] = lrow[tt * 2 + 1];
        }
    }
    #pragma unroll
    for (int tt = 0; tt < 2; ++tt) {
        int r = m0 + tt * 16 + g;
        #pragma unroll
        for (int j = 0; j < 8; ++j) {
            int col = 8 * j + 2 * t;
            size_t pbase = ((size_t)unit * QBLK + r) * HS + col;
            *(uint32_t*)&g_po[pbase] = hpack(acc[tt][j][0], acc[tt][j][1]);
            *(uint32_t*)&g_po[pbase + 8 * HS] = hpack(acc[tt][j][2], acc[tt][j][3]);
        }
    }
}

// ---------------------------------------------------------------------------
// Combine fp16 partials. Grid (32, B, 8): blockIdx.z = 8-col octet.
// ---------------------------------------------------------------------------
__global__ __launch_bounds__(256) void reduce_kernel(float* __restrict__ out) {
    const int mb = blockIdx.x, b = blockIdx.y;
    const int nc = (2 * mb + 2 + CBLK - 1) / CBLK;
    const int tid = threadIdx.x;
    const int r = tid >> 1;
    const int col = blockIdx.z * 8 + (tid & 1) * 4;
    const size_t ubase = ((size_t)(b * 32 + mb)) * NCHUNK;

    float m[NCHUNK], wgt[NCHUNK];
    float mstar = -1e30f;
    #pragma unroll
    for (int c = 0; c < NCHUNK; ++c) {
        if (c < nc) {
            m[c] = g_pm[(ubase + c) * QBLK + r];
            mstar = fmaxf(mstar, m[c]);
        }
    }
    float lsum = 0.f;
    #pragma unroll
    for (int c = 0; c < NCHUNK; ++c) {
        if (c < nc) {
            wgt[c] = exp2f((m[c] - mstar) * CSC);
            lsum += wgt[c] * g_pl[(ubase + c) * QBLK + r];
        }
    }
    float inv = 1.f / lsum;

    float4 o = make_float4(0.f, 0.f, 0.f, 0.f);
    #pragma unroll
    for (int c = 0; c < NCHUNK; ++c) {
        if (c < nc) {
            uint2 pk = *(const uint2*)&g_po[((ubase + c) * QBLK + r) * HS + col];
            float2 p01 = __half22float2(*(__half2*)&pk.x);
            float2 p23 = __half22float2(*(__half2*)&pk.y);
            o.x += wgt[c] * p01.x;
            o.y += wgt[c] * p01.y;
            o.z += wgt[c] * p23.x;
            o.w += wgt[c] * p23.y;
        }
    }
    *(float4*)&out[((size_t)b * T_DIM + mb * QBLK + r) * HS + col] =
        make_float4(o.x * inv, o.y * inv, o.z * inv, o.w * inv);
}

extern "C" void kernel_launch(void* const* d_in, const int* in_sizes, int n_in,
                              void* d_out, int out_size) {
    const float* x = (const float*)d_in[0];
    const float* Wk = (const float*)d_in[1];
    const float* Wv = (const float*)d_in[2];
    float* out = (float*)d_out;

    const int smemProj = 4 * 64 * PB * sizeof(uint16_t);  // 36864
    const int smemAttn = NSTAGE * BUFBYTES;               // 55296
    cudaFuncSetAttribute(proj_kernel, cudaFuncAttributeMaxDynamicSharedMemorySize, smemProj);
    cudaFuncSetAttribute(attn_kernel, cudaFuncAttributeMaxDynamicSharedMemorySize, smemAttn);

    wconv_kernel<<<HS * D_DIM / 512, 256>>>(Wk, Wv);
    proj_kernel<<<(B_DIM * T_DIM) / 64, 128, smemProj>>>(x);
    attn_kernel<<<dim3(32, NCHUNK, B_DIM), 128, smemAttn>>>();
    reduce_kernel<<<dim3(32, B_DIM, 8), 256>>>(out);
}

// round 13
// speedup vs baseline: 1.3525x; 1.0437x over previous
#include <cuda_runtime.h>
#include <cuda_fp16.h>
#include <cstdint>

#define B_DIM 4
#define T_DIM 4096
#define D_DIM 1024
#define HS 64
#define PB 72      // fp16 pitch: conflict-free frag + ldmatrix loads
#define QBLK 128   // q rows per attn CTA
#define NCHUNK 8   // max kv chunks per q-block
#define CBLK 8     // kv blocks (of 64 keys) per chunk

// Projected tensors (fp16). g_qh is pre-scaled by CSC (softmax scale in log2).
__device__ __align__(16) uint16_t g_kh[B_DIM * T_DIM * HS];
__device__ __align__(16) uint16_t g_qh[B_DIM * T_DIM * HS];
__device__ __align__(16) uint16_t g_vth[B_DIM * HS * T_DIM];  // QV^T [b][h][t]

// Preconverted weights: Wk hi; Wv hi/lo
__device__ __align__(16) uint16_t g_wkh[HS * D_DIM];
__device__ __align__(16) uint16_t g_wvh[HS * D_DIM];
__device__ __align__(16) uint16_t g_wvl[HS * D_DIM];

// Split-KV partials
__device__ __align__(16) uint16_t g_po[B_DIM * 32 * NCHUNK * QBLK * HS];  // fp16
__device__ float g_pm[B_DIM * 32 * NCHUNK * QBLK];   // in scaled-log2 domain
__device__ float g_pl[B_DIM * 32 * NCHUNK * QBLK];

#define CSC 0.1803368801111204f  // 0.125 * log2(e)

__device__ __forceinline__ uint32_t hpack(float a, float b) {
    __half2 hh = __floats2half2_rn(a, b);
    return *(uint32_t*)&hh;
}
__device__ __forceinline__ void packpair(float a, float b, uint32_t& h, uint32_t& l) {
    __half2 hh = __floats2half2_rn(a, b);
    h = *(uint32_t*)&hh;
    float2 fb = __half22float2(hh);
    l = hpack(a - fb.x, b - fb.y);
}
__device__ __forceinline__ void mma_f16(float* c, uint32_t a0, uint32_t a1,
                                        uint32_t a2, uint32_t a3,
                                        uint32_t b0, uint32_t b1) {
    asm volatile(
        "mma.sync.aligned.m16n8k16.row.col.f32.f16.f16.f32 "
        "{%0,%1,%2,%3}, {%4,%5,%6,%7}, {%8,%9}, {%0,%1,%2,%3};"
        : "+f"(c[0]), "+f"(c[1]), "+f"(c[2]), "+f"(c[3])
        : "r"(a0), "r"(a1), "r"(a2), "r"(a3), "r"(b0), "r"(b1));
}
__device__ __forceinline__ void ldsm4(uint32_t& r0, uint32_t& r1, uint32_t& r2,
                                      uint32_t& r3, uint32_t addr) {
    asm volatile(
        "ldmatrix.sync.aligned.m8n8.x4.shared.b16 {%0,%1,%2,%3}, [%4];"
        : "=r"(r0), "=r"(r1), "=r"(r2), "=r"(r3) : "r"(addr));
}
__device__ __forceinline__ void cpa16(uint32_t dst, const void* src) {
    asm volatile("cp.async.cg.shared.global [%0], [%1], 16;" :: "r"(dst), "l"(src));
}
#define LD32(arr, idx) (*(const uint32_t*)&(arr)[idx])

// ---------------------------------------------------------------------------
// One-time weight conversion fp32 -> fp16 (Wk hi; Wv hi/lo)
// ---------------------------------------------------------------------------
__global__ __launch_bounds__(256) void wconv_kernel(const float* __restrict__ Wk,
                                                    const float* __restrict__ Wv) {
    int i = blockIdx.x * 512 + threadIdx.x * 2;
    *(uint32_t*)&g_wkh[i] = hpack(Wk[i], Wk[i + 1]);
    uint32_t h, l;
    packpair(Wv[i], Wv[i + 1], h, l);
    *(uint32_t*)&g_wvh[i] = h;
    *(uint32_t*)&g_wvl[i] = l;
}

// ---------------------------------------------------------------------------
// Projection: 64-row CTAs, 128 thr, 3 CTAs/SM.
// k = xh@Wkh^T (1-MMA), qv = xh@(Wvh+Wvl)^T (2-MMA). g_qh scaled by CSC.
// ---------------------------------------------------------------------------
__global__ __launch_bounds__(128, 3) void proj_kernel(const float* __restrict__ x) {
    extern __shared__ __align__(16) uint16_t sm[];
    uint16_t* sXh = sm;
    uint16_t* sWk = sXh + 64 * PB;
    uint16_t* sWvh = sWk + 64 * PB;
    uint16_t* sWvl = sWvh + 64 * PB;
    const uint32_t smb = (uint32_t)__cvta_generic_to_shared(sm);
    const uint32_t AB = 64 * PB * 2;

    const int tid = threadIdx.x;
    const int w = tid >> 5, lane = tid & 31, g = lane >> 2, t = lane & 3;
    const int RB = blockIdx.x * 64;
    const int m0 = w * 16;

    float accK[8][4] = {};
    float accV[8][4] = {};

    for (int d0 = 0; d0 < D_DIM; d0 += 64) {
        __syncthreads();
        #pragma unroll
        for (int l = 0; l < 4; ++l) {
            int id = tid + l * 128;
            int r = id >> 3, c8 = (id & 7) * 8;
            uint32_t soff = (uint32_t)(r * PB + c8) * 2;
            size_t go = (size_t)r * D_DIM + d0 + c8;
            cpa16(smb + AB + soff, &g_wkh[go]);
            cpa16(smb + 2 * AB + soff, &g_wvh[go]);
            cpa16(smb + 3 * AB + soff, &g_wvl[go]);
        }
        asm volatile("cp.async.commit_group;");
        #pragma unroll
        for (int l = 0; l < 8; ++l) {
            int idx = tid + l * 128;
            int r = idx >> 4, c = (idx & 15) * 4;
            float4 fx = *(const float4*)&x[(size_t)(RB + r) * D_DIM + d0 + c];
            *(uint32_t*)&sXh[r * PB + c] = hpack(fx.x, fx.y);
            *(uint32_t*)&sXh[r * PB + c + 2] = hpack(fx.z, fx.w);
        }
        asm volatile("cp.async.wait_group 0;" ::: "memory");
        __syncthreads();

        #pragma unroll
        for (int k0 = 0; k0 < 64; k0 += 16) {
            int ra = (m0 + g) * PB + k0 + 2 * t;
            uint32_t ah0 = LD32(sXh, ra);
            uint32_t ah1 = LD32(sXh, ra + 8 * PB);
            uint32_t ah2 = LD32(sXh, ra + 8);
            uint32_t ah3 = LD32(sXh, ra + 8 * PB + 8);
            #pragma unroll
            for (int j = 0; j < 8; ++j) {
                int rb = (8 * j + g) * PB + k0 + 2 * t;
                uint32_t k0r = LD32(sWk, rb), k1r = LD32(sWk, rb + 8);
                mma_f16(accK[j], ah0, ah1, ah2, ah3, k0r, k1r);
                uint32_t vh0 = LD32(sWvh, rb), vh1 = LD32(sWvh, rb + 8);
                uint32_t vl0 = LD32(sWvl, rb), vl1 = LD32(sWvl, rb + 8);
                mma_f16(accV[j], ah0, ah1, ah2, ah3, vh0, vh1);
                mma_f16(accV[j], ah0, ah1, ah2, ah3, vl0, vl1);
            }
        }
    }

    const int row0 = RB + m0 + g;
    const int batch = row0 / T_DIM;
    const int tl0 = row0 % T_DIM;

    #pragma unroll
    for (int j = 0; j < 8; ++j) {
        int col = 8 * j + 2 * t;
        *(uint32_t*)&g_kh[(size_t)row0 * HS + col] = hpack(accK[j][0], accK[j][1]);
        *(uint32_t*)&g_kh[(size_t)(row0 + 8) * HS + col] = hpack(accK[j][2], accK[j][3]);
        // Q: pre-scaled by CSC (softmax scale folded into QK scores)
        *(uint32_t*)&g_qh[(size_t)row0 * HS + col] =
            hpack(accV[j][0] * CSC, accV[j][1] * CSC);
        *(uint32_t*)&g_qh[(size_t)(row0 + 8) * HS + col] =
            hpack(accV[j][2] * CSC, accV[j][3] * CSC);
        #pragma unroll
        for (int q = 0; q < 4; ++q) {
            float v = accV[j][q];
            int cc = col + (q & 1);
            int tt = tl0 + (q >> 1) * 8;
            __half hv = __float2half_rn(v);
            g_vth[((size_t)batch * HS + cc) * T_DIM + tt] = *(uint16_t*)&hv;
        }
    }
}

// ---------------------------------------------------------------------------
// Split-KV flash attention, QBLK=128, ldmatrix fragment loads.
// ---------------------------------------------------------------------------
#define ABYTES (64 * PB * 2)
#define BUFBYTES (2 * ABYTES)   // Kh, Vth
#define AU16 (64 * PB)
#define NSTAGE 3

__global__ __launch_bounds__(128, 2) void attn_kernel() {
    const int mblk = 31 - blockIdx.x;          // longest-first
    const int kbLast = 2 * mblk + 1;
    const int kb0 = blockIdx.y * CBLK;
    if (kb0 > kbLast) return;
    const int kb1 = min(kb0 + CBLK - 1, kbLast);
    const int b = blockIdx.z;
    const int unit = (b * 32 + mblk) * NCHUNK + blockIdx.y;

    extern __shared__ __align__(16) uint16_t sm[];
    const uint32_t smb = (uint32_t)__cvta_generic_to_shared(sm);

    const int tid = threadIdx.x;
    const int w = tid >> 5, lane = tid & 31, g = lane >> 2, t = lane & 3;
    const int qRow = mblk * QBLK;
    const int m0 = w * 32;
    const int lr = tid >> 3;
    const int lc = (tid & 7) * 8;

    // ldmatrix per-lane byte offset: tile = lane>>3 (2 j-subtiles x 2 k-halves)
    const uint32_t laneK =
        (uint32_t)(((lane >> 4) * 8 * PB) + ((lane & 7) * PB) + (((lane >> 3) & 1) * 8)) * 2;

    // Q A-fragments (single fp16, pre-scaled), two row tiles
    uint32_t q[2][4][4];
    {
        const uint16_t* Qh = g_qh + (size_t)b * T_DIM * HS;
        #pragma unroll
        for (int tt = 0; tt < 2; ++tt) {
            int base = (qRow + m0 + tt * 16 + g) * HS + 2 * t;
            #pragma unroll
            for (int kk = 0; kk < 4; ++kk) {
                int o = base + kk * 16;
                q[tt][kk][0] = LD32(Qh, o);
                q[tt][kk][1] = LD32(Qh, o + 8 * HS);
                q[tt][kk][2] = LD32(Qh, o + 8);
                q[tt][kk][3] = LD32(Qh, o + 8 * HS + 8);
            }
        }
    }

    auto issue_tile = [&](int kb) {
        uint32_t base = smb + (uint32_t)(kb % NSTAGE) * BUFBYTES;
        #pragma unroll
        for (int l = 0; l < 4; ++l) {
            int r = lr + l * 16;
            uint32_t soff = (uint32_t)(r * PB + lc) * 2;
            size_t gk = ((size_t)b * T_DIM + kb * 64 + r) * HS + lc;
            cpa16(base + soff, &g_kh[gk]);
            size_t gv = ((size_t)b * HS + r) * T_DIM + kb * 64 + lc;
            cpa16(base + ABYTES + soff, &g_vth[gv]);
        }
        asm volatile("cp.async.commit_group;");
    };

    issue_tile(kb0);
    if (kb0 + 1 <= kb1) issue_tile(kb0 + 1);

    float acc[2][8][4] = {};
    float mrow[4] = {-1e30f, -1e30f, -1e30f, -1e30f};
    float lrow[4] = {0.f, 0.f, 0.f, 0.f};

    for (int kb = kb0; kb <= kb1; ++kb) {
        if (kb < kb1) {
            asm volatile("cp.async.wait_group 1;" ::: "memory");
        } else {
            asm volatile("cp.async.wait_group 0;" ::: "memory");
        }
        __syncthreads();
        if (kb + 2 <= kb1) issue_tile(kb + 2);

        const uint32_t kBase = smb + (uint32_t)(kb % NSTAGE) * BUFBYTES + laneK;
        const uint32_t vBase = kBase + ABYTES;

        // S = Q @ K^T, K fragments via ldmatrix.x4 (2 j per call)
        float s[2][8][4] = {};
        #pragma unroll
        for (int kk = 0; kk < 4; ++kk) {
            #pragma unroll
            for (int jp = 0; jp < 4; ++jp) {
                uint32_t b0, b1, b2, b3;
                ldsm4(b0, b1, b2, b3,
                      kBase + (uint32_t)((jp * 16 * PB + kk * 16) * 2));
                mma_f16(s[0][2 * jp], q[0][kk][0], q[0][kk][1], q[0][kk][2], q[0][kk][3], b0, b1);
                mma_f16(s[1][2 * jp], q[1][kk][0], q[1][kk][1], q[1][kk][2], q[1][kk][3], b0, b1);
                mma_f16(s[0][2 * jp + 1], q[0][kk][0], q[0][kk][1], q[0][kk][2], q[0][kk][3], b2, b3);
                mma_f16(s[1][2 * jp + 1], q[1][kk][0], q[1][kk][1], q[1][kk][2], q[1][kk][3], b2, b3);
            }
        }

        // causal mask: only last two kv blocks overlap the diagonal
        if (kb >= 2 * mblk) {
            const int off = qRow - kb * 64;
            #pragma unroll
            for (int tt = 0; tt < 2; ++tt) {
                int r0l = m0 + tt * 16 + g + off, r1l = r0l + 8;
                #pragma unroll
                for (int j = 0; j < 8; ++j) {
                    int c0 = 8 * j + 2 * t, c1 = c0 + 1;
                    if (c0 > r0l) s[tt][j][0] = -1e30f;
                    if (c1 > r0l) s[tt][j][1] = -1e30f;
                    if (c0 > r1l) s[tt][j][2] = -1e30f;
                    if (c1 > r1l) s[tt][j][3] = -1e30f;
                }
            }
        }

        // online softmax (scores already in log2 domain; no scale multiply)
        #pragma unroll
        for (int tt = 0; tt < 2; ++tt) {
            float mx0 = -1e30f, mx1 = -1e30f;
            #pragma unroll
            for (int j = 0; j < 8; ++j) {
                mx0 = fmaxf(mx0, fmaxf(s[tt][j][0], s[tt][j][1]));
                mx1 = fmaxf(mx1, fmaxf(s[tt][j][2], s[tt][j][3]));
            }
            mx0 = fmaxf(mx0, __shfl_xor_sync(0xffffffffu, mx0, 1));
            mx0 = fmaxf(mx0, __shfl_xor_sync(0xffffffffu, mx0, 2));
            mx1 = fmaxf(mx1, __shfl_xor_sync(0xffffffffu, mx1, 1));
            mx1 = fmaxf(mx1, __shfl_xor_sync(0xffffffffu, mx1, 2));
            float mn0 = fmaxf(mrow[tt * 2], mx0), mn1 = fmaxf(mrow[tt * 2 + 1], mx1);
            float cr0 = exp2f(mrow[tt * 2] - mn0);
            float cr1 = exp2f(mrow[tt * 2 + 1] - mn1);
            float sum0 = 0.f, sum1 = 0.f;
            #pragma unroll
            for (int j = 0; j < 8; ++j) {
                s[tt][j][0] = exp2f(s[tt][j][0] - mn0);
                s[tt][j][1] = exp2f(s[tt][j][1] - mn0);
                s[tt][j][2] = exp2f(s[tt][j][2] - mn1);
                s[tt][j][3] = exp2f(s[tt][j][3] - mn1);
                sum0 += s[tt][j][0] + s[tt][j][1];
                sum1 += s[tt][j][2] + s[tt][j][3];
            }
            sum0 += __shfl_xor_sync(0xffffffffu, sum0, 1);
            sum0 += __shfl_xor_sync(0xffffffffu, sum0, 2);
            sum1 += __shfl_xor_sync(0xffffffffu, sum1, 1);
            sum1 += __shfl_xor_sync(0xffffffffu, sum1, 2);
            lrow[tt * 2] = lrow[tt * 2] * cr0 + sum0;
            lrow[tt * 2 + 1] = lrow[tt * 2 + 1] * cr1 + sum1;
            mrow[tt * 2] = mn0;
            mrow[tt * 2 + 1] = mn1;
            #pragma unroll
            for (int j = 0; j < 8; ++j) {
                acc[tt][j][0] *= cr0;
                acc[tt][j][1] *= cr0;
                acc[tt][j][2] *= cr1;
                acc[tt][j][3] *= cr1;
            }
        }

        // P (hi) x V, V fragments via ldmatrix.x4
        #pragma unroll
        for (int kk = 0; kk < 4; ++kk) {
            uint32_t ph[2][4];
            #pragma unroll
            for (int tt = 0; tt < 2; ++tt) {
                float* pA = s[tt][2 * kk];
                float* pB = s[tt][2 * kk + 1];
                ph[tt][0] = hpack(pA[0], pA[1]);
                ph[tt][1] = hpack(pA[2], pA[3]);
                ph[tt][2] = hpack(pB[0], pB[1]);
                ph[tt][3] = hpack(pB[2], pB[3]);
            }
            #pragma unroll
            for (int jp = 0; jp < 4; ++jp) {
                uint32_t v0, v1, v2, v3;
                ldsm4(v0, v1, v2, v3,
                      vBase + (uint32_t)((jp * 16 * PB + kk * 16) * 2));
                mma_f16(acc[0][2 * jp], ph[0][0], ph[0][1], ph[0][2], ph[0][3], v0, v1);
                mma_f16(acc[1][2 * jp], ph[1][0], ph[1][1], ph[1][2], ph[1][3], v0, v1);
                mma_f16(acc[0][2 * jp + 1], ph[0][0], ph[0][1], ph[0][2], ph[0][3], v2, v3);
                mma_f16(acc[1][2 * jp + 1], ph[1][0], ph[1][1], ph[1][2], ph[1][3], v2, v3);
            }
        }
    }

    // write partials (O as fp16; m in scaled-log2 domain)
    if (t == 0) {
        #pragma unroll
        for (int tt = 0; tt < 2; ++tt) {
            int r = m0 + tt * 16 + g;
            g_pm[(size_t)unit * QBLK + r] = mrow[tt * 2];
            g_pm[(size_t)unit * QBLK + r + 8] = mrow[tt * 2 + 1];
            g_pl[(size_t)unit * QBLK + r] = lrow[tt * 2];
            g_pl[(size_t)unit * QBLK + r + 8] = lrow[tt * 2 + 1];
        }
    }
    #pragma unroll
    for (int tt = 0; tt < 2; ++tt) {
        int r = m0 + tt * 16 + g;
        #pragma unroll
        for (int j = 0; j < 8; ++j) {
            int col = 8 * j + 2 * t;
            size_t pbase = ((size_t)unit * QBLK + r) * HS + col;
            *(uint32_t*)&g_po[pbase] = hpack(acc[tt][j][0], acc[tt][j][1]);
            *(uint32_t*)&g_po[pbase + 8 * HS] = hpack(acc[tt][j][2], acc[tt][j][3]);
        }
    }
}

// ---------------------------------------------------------------------------
// Combine fp16 partials. Grid (32, B, 8). m already in log2 domain.
// ---------------------------------------------------------------------------
__global__ __launch_bounds__(256) void reduce_kernel(float* __restrict__ out) {
    const int mb = blockIdx.x, b = blockIdx.y;
    const int nc = (2 * mb + 2 + CBLK - 1) / CBLK;
    const int tid = threadIdx.x;
    const int r = tid >> 1;
    const int col = blockIdx.z * 8 + (tid & 1) * 4;
    const size_t ubase = ((size_t)(b * 32 + mb)) * NCHUNK;

    float m[NCHUNK], wgt[NCHUNK];
    float mstar = -1e30f;
    #pragma unroll
    for (int c = 0; c < NCHUNK; ++c) {
        if (c < nc) {
            m[c] = g_pm[(ubase + c) * QBLK + r];
            mstar = fmaxf(mstar, m[c]);
        }
    }
    float lsum = 0.f;
    #pragma unroll
    for (int c = 0; c < NCHUNK; ++c) {
        if (c < nc) {
            wgt[c] = exp2f(m[c] - mstar);
            lsum += wgt[c] * g_pl[(ubase + c) * QBLK + r];
        }
    }
    float inv = 1.f / lsum;

    float4 o = make_float4(0.f, 0.f, 0.f, 0.f);
    #pragma unroll
    for (int c = 0; c < NCHUNK; ++c) {
        if (c < nc) {
            uint2 pk = *(const uint2*)&g_po[((ubase + c) * QBLK + r) * HS + col];
            float2 p01 = __half22float2(*(__half2*)&pk.x);
            float2 p23 = __half22float2(*(__half2*)&pk.y);
            o.x += wgt[c] * p01.x;
            o.y += wgt[c] * p01.y;
            o.z += wgt[c] * p23.x;
            o.w += wgt[c] * p23.y;
        }
    }
    *(float4*)&out[((size_t)b * T_DIM + mb * QBLK + r) * HS + col] =
        make_float4(o.x * inv, o.y * inv, o.z * inv, o.w * inv);
}

extern "C" void kernel_launch(void* const* d_in, const int* in_sizes, int n_in,
                              void* d_out, int out_size) {
    const float* x = (const float*)d_in[0];
    const float* Wk = (const float*)d_in[1];
    const float* Wv = (const float*)d_in[2];
    float* out = (float*)d_out;

    const int smemProj = 4 * 64 * PB * sizeof(uint16_t);  // 36864
    const int smemAttn = NSTAGE * BUFBYTES;               // 55296
    cudaFuncSetAttribute(proj_kernel, cudaFuncAttributeMaxDynamicSharedMemorySize, smemProj);
    cudaFuncSetAttribute(attn_kernel, cudaFuncAttributeMaxDynamicSharedMemorySize, smemAttn);

    wconv_kernel<<<HS * D_DIM / 512, 256>>>(Wk, Wv);
    proj_kernel<<<(B_DIM * T_DIM) / 64, 128, smemProj>>>(x);
    attn_kernel<<<dim3(32, NCHUNK, B_DIM), 128, smemAttn>>>();
    reduce_kernel<<<dim3(32, B_DIM, 8), 256>>>(out);
}

// round 14
// speedup vs baseline: 1.3917x; 1.0290x over previous
#include <cuda_runtime.h>
#include <cuda_fp16.h>
#include <cstdint>

#define B_DIM 4
#define T_DIM 4096
#define D_DIM 1024
#define HS 64
#define PB 72      // fp16 pitch: conflict-free frag + ldmatrix loads
#define QBLK 128   // q rows per attn CTA
#define NCHUNK 4   // max kv chunks per q-block
#define CBLK 16    // kv blocks (of 64 keys) per chunk

// Projected tensors (fp16). g_qh is pre-scaled by CSC (softmax scale in log2).
__device__ __align__(16) uint16_t g_kh[B_DIM * T_DIM * HS];
__device__ __align__(16) uint16_t g_qh[B_DIM * T_DIM * HS];
__device__ __align__(16) uint16_t g_vth[B_DIM * HS * T_DIM];  // QV^T [b][h][t]

// Preconverted weights: Wk hi; Wv hi/lo
__device__ __align__(16) uint16_t g_wkh[HS * D_DIM];
__device__ __align__(16) uint16_t g_wvh[HS * D_DIM];
__device__ __align__(16) uint16_t g_wvl[HS * D_DIM];

// Split-KV partials
__device__ __align__(16) uint16_t g_po[B_DIM * 32 * NCHUNK * QBLK * HS];  // fp16
__device__ float g_pm[B_DIM * 32 * NCHUNK * QBLK];   // in scaled-log2 domain
__device__ float g_pl[B_DIM * 32 * NCHUNK * QBLK];

#define CSC 0.1803368801111204f  // 0.125 * log2(e)

__device__ __forceinline__ uint32_t hpack(float a, float b) {
    __half2 hh = __floats2half2_rn(a, b);
    return *(uint32_t*)&hh;
}
__device__ __forceinline__ void packpair(float a, float b, uint32_t& h, uint32_t& l) {
    __half2 hh = __floats2half2_rn(a, b);
    h = *(uint32_t*)&hh;
    float2 fb = __half22float2(hh);
    l = hpack(a - fb.x, b - fb.y);
}
__device__ __forceinline__ void mma_f16(float* c, uint32_t a0, uint32_t a1,
                                        uint32_t a2, uint32_t a3,
                                        uint32_t b0, uint32_t b1) {
    asm volatile(
        "mma.sync.aligned.m16n8k16.row.col.f32.f16.f16.f32 "
        "{%0,%1,%2,%3}, {%4,%5,%6,%7}, {%8,%9}, {%0,%1,%2,%3};"
        : "+f"(c[0]), "+f"(c[1]), "+f"(c[2]), "+f"(c[3])
        : "r"(a0), "r"(a1), "r"(a2), "r"(a3), "r"(b0), "r"(b1));
}
__device__ __forceinline__ void ldsm4(uint32_t& r0, uint32_t& r1, uint32_t& r2,
                                      uint32_t& r3, uint32_t addr) {
    asm volatile(
        "ldmatrix.sync.aligned.m8n8.x4.shared.b16 {%0,%1,%2,%3}, [%4];"
        : "=r"(r0), "=r"(r1), "=r"(r2), "=r"(r3) : "r"(addr));
}
__device__ __forceinline__ void cpa16(uint32_t dst, const void* src) {
    asm volatile("cp.async.cg.shared.global [%0], [%1], 16;" :: "r"(dst), "l"(src));
}
#define LD32(arr, idx) (*(const uint32_t*)&(arr)[idx])

// ---------------------------------------------------------------------------
// One-time weight conversion fp32 -> fp16 (Wk hi; Wv hi/lo)
// ---------------------------------------------------------------------------
__global__ __launch_bounds__(256) void wconv_kernel(const float* __restrict__ Wk,
                                                    const float* __restrict__ Wv) {
    int i = blockIdx.x * 512 + threadIdx.x * 2;
    *(uint32_t*)&g_wkh[i] = hpack(Wk[i], Wk[i + 1]);
    uint32_t h, l;
    packpair(Wv[i], Wv[i + 1], h, l);
    *(uint32_t*)&g_wvh[i] = h;
    *(uint32_t*)&g_wvl[i] = l;
}

// ---------------------------------------------------------------------------
// Projection: 64-row CTAs, 128 thr, 3 CTAs/SM.
// k = xh@Wkh^T (1-MMA), qv = xh@(Wvh+Wvl)^T (2-MMA). g_qh scaled by CSC.
// ---------------------------------------------------------------------------
__global__ __launch_bounds__(128, 3) void proj_kernel(const float* __restrict__ x) {
    extern __shared__ __align__(16) uint16_t sm[];
    uint16_t* sXh = sm;
    uint16_t* sWk = sXh + 64 * PB;
    uint16_t* sWvh = sWk + 64 * PB;
    uint16_t* sWvl = sWvh + 64 * PB;
    const uint32_t smb = (uint32_t)__cvta_generic_to_shared(sm);
    const uint32_t AB = 64 * PB * 2;

    const int tid = threadIdx.x;
    const int w = tid >> 5, lane = tid & 31, g = lane >> 2, t = lane & 3;
    const int RB = blockIdx.x * 64;
    const int m0 = w * 16;

    float accK[8][4] = {};
    float accV[8][4] = {};

    for (int d0 = 0; d0 < D_DIM; d0 += 64) {
        __syncthreads();
        #pragma unroll
        for (int l = 0; l < 4; ++l) {
            int id = tid + l * 128;
            int r = id >> 3, c8 = (id & 7) * 8;
            uint32_t soff = (uint32_t)(r * PB + c8) * 2;
            size_t go = (size_t)r * D_DIM + d0 + c8;
            cpa16(smb + AB + soff, &g_wkh[go]);
            cpa16(smb + 2 * AB + soff, &g_wvh[go]);
            cpa16(smb + 3 * AB + soff, &g_wvl[go]);
        }
        asm volatile("cp.async.commit_group;");
        #pragma unroll
        for (int l = 0; l < 8; ++l) {
            int idx = tid + l * 128;
            int r = idx >> 4, c = (idx & 15) * 4;
            float4 fx = *(const float4*)&x[(size_t)(RB + r) * D_DIM + d0 + c];
            *(uint32_t*)&sXh[r * PB + c] = hpack(fx.x, fx.y);
            *(uint32_t*)&sXh[r * PB + c + 2] = hpack(fx.z, fx.w);
        }
        asm volatile("cp.async.wait_group 0;" ::: "memory");
        __syncthreads();

        #pragma unroll
        for (int k0 = 0; k0 < 64; k0 += 16) {
            int ra = (m0 + g) * PB + k0 + 2 * t;
            uint32_t ah0 = LD32(sXh, ra);
            uint32_t ah1 = LD32(sXh, ra + 8 * PB);
            uint32_t ah2 = LD32(sXh, ra + 8);
            uint32_t ah3 = LD32(sXh, ra + 8 * PB + 8);
            #pragma unroll
            for (int j = 0; j < 8; ++j) {
                int rb = (8 * j + g) * PB + k0 + 2 * t;
                uint32_t k0r = LD32(sWk, rb), k1r = LD32(sWk, rb + 8);
                mma_f16(accK[j], ah0, ah1, ah2, ah3, k0r, k1r);
                uint32_t vh0 = LD32(sWvh, rb), vh1 = LD32(sWvh, rb + 8);
                uint32_t vl0 = LD32(sWvl, rb), vl1 = LD32(sWvl, rb + 8);
                mma_f16(accV[j], ah0, ah1, ah2, ah3, vh0, vh1);
                mma_f16(accV[j], ah0, ah1, ah2, ah3, vl0, vl1);
            }
        }
    }

    const int row0 = RB + m0 + g;
    const int batch = row0 / T_DIM;
    const int tl0 = row0 % T_DIM;

    #pragma unroll
    for (int j = 0; j < 8; ++j) {
        int col = 8 * j + 2 * t;
        *(uint32_t*)&g_kh[(size_t)row0 * HS + col] = hpack(accK[j][0], accK[j][1]);
        *(uint32_t*)&g_kh[(size_t)(row0 + 8) * HS + col] = hpack(accK[j][2], accK[j][3]);
        *(uint32_t*)&g_qh[(size_t)row0 * HS + col] =
            hpack(accV[j][0] * CSC, accV[j][1] * CSC);
        *(uint32_t*)&g_qh[(size_t)(row0 + 8) * HS + col] =
            hpack(accV[j][2] * CSC, accV[j][3] * CSC);
        #pragma unroll
        for (int q = 0; q < 4; ++q) {
            float v = accV[j][q];
            int cc = col + (q & 1);
            int tt = tl0 + (q >> 1) * 8;
            __half hv = __float2half_rn(v);
            g_vth[((size_t)batch * HS + cc) * T_DIM + tt] = *(uint16_t*)&hv;
        }
    }
}

// ---------------------------------------------------------------------------
// Split-KV flash attention, QBLK=128, ldmatrix fragment loads.
// ---------------------------------------------------------------------------
#define ABYTES (64 * PB * 2)
#define BUFBYTES (2 * ABYTES)   // Kh, Vth
#define AU16 (64 * PB)
#define NSTAGE 3

__global__ __launch_bounds__(128, 2) void attn_kernel() {
    const int mblk = 31 - blockIdx.x;          // longest-first
    const int kbLast = 2 * mblk + 1;
    const int kb0 = blockIdx.y * CBLK;
    if (kb0 > kbLast) return;
    const int kb1 = min(kb0 + CBLK - 1, kbLast);
    const int b = blockIdx.z;
    const int unit = (b * 32 + mblk) * NCHUNK + blockIdx.y;

    extern __shared__ __align__(16) uint16_t sm[];
    const uint32_t smb = (uint32_t)__cvta_generic_to_shared(sm);

    const int tid = threadIdx.x;
    const int w = tid >> 5, lane = tid & 31, g = lane >> 2, t = lane & 3;
    const int qRow = mblk * QBLK;
    const int m0 = w * 32;
    const int lr = tid >> 3;
    const int lc = (tid & 7) * 8;

    // ldmatrix per-lane byte offset: tile = lane>>3 (2 j-subtiles x 2 k-halves)
    const uint32_t laneK =
        (uint32_t)(((lane >> 4) * 8 * PB) + ((lane & 7) * PB) + (((lane >> 3) & 1) * 8)) * 2;

    // Q A-fragments (single fp16, pre-scaled), two row tiles
    uint32_t q[2][4][4];
    {
        const uint16_t* Qh = g_qh + (size_t)b * T_DIM * HS;
        #pragma unroll
        for (int tt = 0; tt < 2; ++tt) {
            int base = (qRow + m0 + tt * 16 + g) * HS + 2 * t;
            #pragma unroll
            for (int kk = 0; kk < 4; ++kk) {
                int o = base + kk * 16;
                q[tt][kk][0] = LD32(Qh, o);
                q[tt][kk][1] = LD32(Qh, o + 8 * HS);
                q[tt][kk][2] = LD32(Qh, o + 8);
                q[tt][kk][3] = LD32(Qh, o + 8 * HS + 8);
            }
        }
    }

    auto issue_tile = [&](int kb) {
        uint32_t base = smb + (uint32_t)(kb % NSTAGE) * BUFBYTES;
        #pragma unroll
        for (int l = 0; l < 4; ++l) {
            int r = lr + l * 16;
            uint32_t soff = (uint32_t)(r * PB + lc) * 2;
            size_t gk = ((size_t)b * T_DIM + kb * 64 + r) * HS + lc;
            cpa16(base + soff, &g_kh[gk]);
            size_t gv = ((size_t)b * HS + r) * T_DIM + kb * 64 + lc;
            cpa16(base + ABYTES + soff, &g_vth[gv]);
        }
        asm volatile("cp.async.commit_group;");
    };

    issue_tile(kb0);
    if (kb0 + 1 <= kb1) issue_tile(kb0 + 1);

    float acc[2][8][4] = {};
    float mrow[4] = {-1e30f, -1e30f, -1e30f, -1e30f};
    float lrow[4] = {0.f, 0.f, 0.f, 0.f};

    for (int kb = kb0; kb <= kb1; ++kb) {
        if (kb < kb1) {
            asm volatile("cp.async.wait_group 1;" ::: "memory");
        } else {
            asm volatile("cp.async.wait_group 0;" ::: "memory");
        }
        __syncthreads();
        if (kb + 2 <= kb1) issue_tile(kb + 2);

        const uint32_t kBase = smb + (uint32_t)(kb % NSTAGE) * BUFBYTES + laneK;
        const uint32_t vBase = kBase + ABYTES;

        // S = Q @ K^T, K fragments via ldmatrix.x4 (2 j per call)
        float s[2][8][4] = {};
        #pragma unroll
        for (int kk = 0; kk < 4; ++kk) {
            #pragma unroll
            for (int jp = 0; jp < 4; ++jp) {
                uint32_t b0, b1, b2, b3;
                ldsm4(b0, b1, b2, b3,
                      kBase + (uint32_t)((jp * 16 * PB + kk * 16) * 2));
                mma_f16(s[0][2 * jp], q[0][kk][0], q[0][kk][1], q[0][kk][2], q[0][kk][3], b0, b1);
                mma_f16(s[1][2 * jp], q[1][kk][0], q[1][kk][1], q[1][kk][2], q[1][kk][3], b0, b1);
                mma_f16(s[0][2 * jp + 1], q[0][kk][0], q[0][kk][1], q[0][kk][2], q[0][kk][3], b2, b3);
                mma_f16(s[1][2 * jp + 1], q[1][kk][0], q[1][kk][1], q[1][kk][2], q[1][kk][3], b2, b3);
            }
        }

        // causal mask: only last two kv blocks overlap the diagonal
        if (kb >= 2 * mblk) {
            const int off = qRow - kb * 64;
            #pragma unroll
            for (int tt = 0; tt < 2; ++tt) {
                int r0l = m0 + tt * 16 + g + off, r1l = r0l + 8;
                #pragma unroll
                for (int j = 0; j < 8; ++j) {
                    int c0 = 8 * j + 2 * t, c1 = c0 + 1;
                    if (c0 > r0l) s[tt][j][0] = -1e30f;
                    if (c1 > r0l) s[tt][j][1] = -1e30f;
                    if (c0 > r1l) s[tt][j][2] = -1e30f;
                    if (c1 > r1l) s[tt][j][3] = -1e30f;
                }
            }
        }

        // online softmax (scores already in log2 domain; no scale multiply)
        #pragma unroll
        for (int tt = 0; tt < 2; ++tt) {
            float mx0 = -1e30f, mx1 = -1e30f;
            #pragma unroll
            for (int j = 0; j < 8; ++j) {
                mx0 = fmaxf(mx0, fmaxf(s[tt][j][0], s[tt][j][1]));
                mx1 = fmaxf(mx1, fmaxf(s[tt][j][2], s[tt][j][3]));
            }
            mx0 = fmaxf(mx0, __shfl_xor_sync(0xffffffffu, mx0, 1));
            mx0 = fmaxf(mx0, __shfl_xor_sync(0xffffffffu, mx0, 2));
            mx1 = fmaxf(mx1, __shfl_xor_sync(0xffffffffu, mx1, 1));
            mx1 = fmaxf(mx1, __shfl_xor_sync(0xffffffffu, mx1, 2));
            float mn0 = fmaxf(mrow[tt * 2], mx0), mn1 = fmaxf(mrow[tt * 2 + 1], mx1);
            float cr0 = exp2f(mrow[tt * 2] - mn0);
            float cr1 = exp2f(mrow[tt * 2 + 1] - mn1);
            float sum0 = 0.f, sum1 = 0.f;
            #pragma unroll
            for (int j = 0; j < 8; ++j) {
                s[tt][j][0] = exp2f(s[tt][j][0] - mn0);
                s[tt][j][1] = exp2f(s[tt][j][1] - mn0);
                s[tt][j][2] = exp2f(s[tt][j][2] - mn1);
                s[tt][j][3] = exp2f(s[tt][j][3] - mn1);
                sum0 += s[tt][j][0] + s[tt][j][1];
                sum1 += s[tt][j][2] + s[tt][j][3];
            }
            sum0 += __shfl_xor_sync(0xffffffffu, sum0, 1);
            sum0 += __shfl_xor_sync(0xffffffffu, sum0, 2);
            sum1 += __shfl_xor_sync(0xffffffffu, sum1, 1);
            sum1 += __shfl_xor_sync(0xffffffffu, sum1, 2);
            lrow[tt * 2] = lrow[tt * 2] * cr0 + sum0;
            lrow[tt * 2 + 1] = lrow[tt * 2 + 1] * cr1 + sum1;
            mrow[tt * 2] = mn0;
            mrow[tt * 2 + 1] = mn1;
            #pragma unroll
            for (int j = 0; j < 8; ++j) {
                acc[tt][j][0] *= cr0;
                acc[tt][j][1] *= cr0;
                acc[tt][j][2] *= cr1;
                acc[tt][j][3] *= cr1;
            }
        }

        // P (hi) x V, V fragments via ldmatrix.x4
        #pragma unroll
        for (int kk = 0; kk < 4; ++kk) {
            uint32_t ph[2][4];
            #pragma unroll
            for (int tt = 0; tt < 2; ++tt) {
                float* pA = s[tt][2 * kk];
                float* pB = s[tt][2 * kk + 1];
                ph[tt][0] = hpack(pA[0], pA[1]);
                ph[tt][1] = hpack(pA[2], pA[3]);
                ph[tt][2] = hpack(pB[0], pB[1]);
                ph[tt][3] = hpack(pB[2], pB[3]);
            }
            #pragma unroll
            for (int jp = 0; jp < 4; ++jp) {
                uint32_t v0, v1, v2, v3;
                ldsm4(v0, v1, v2, v3,
                      vBase + (uint32_t)((jp * 16 * PB + kk * 16) * 2));
                mma_f16(acc[0][2 * jp], ph[0][0], ph[0][1], ph[0][2], ph[0][3], v0, v1);
                mma_f16(acc[1][2 * jp], ph[1][0], ph[1][1], ph[1][2], ph[1][3], v0, v1);
                mma_f16(acc[0][2 * jp + 1], ph[0][0], ph[0][1], ph[0][2], ph[0][3], v2, v3);
                mma_f16(acc[1][2 * jp + 1], ph[1][0], ph[1][1], ph[1][2], ph[1][3], v2, v3);
            }
        }
    }

    // write partials (O as fp16; m in scaled-log2 domain)
    if (t == 0) {
        #pragma unroll
        for (int tt = 0; tt < 2; ++tt) {
            int r = m0 + tt * 16 + g;
            g_pm[(size_t)unit * QBLK + r] = mrow[tt * 2];
            g_pm[(size_t)unit * QBLK + r + 8] = mrow[tt * 2 + 1];
            g_pl[(size_t)unit * QBLK + r] = lrow[tt * 2];
            g_pl[(size_t)unit * QBLK + r + 8] = lrow[tt * 2 + 1];
        }
    }
    #pragma unroll
    for (int tt = 0; tt < 2; ++tt) {
        int r = m0 + tt * 16 + g;
        #pragma unroll
        for (int j = 0; j < 8; ++j) {
            int col = 8 * j + 2 * t;
            size_t pbase = ((size_t)unit * QBLK + r) * HS + col;
            *(uint32_t*)&g_po[pbase] = hpack(acc[tt][j][0], acc[tt][j][1]);
            *(uint32_t*)&g_po[pbase + 8 * HS] = hpack(acc[tt][j][2], acc[tt][j][3]);
        }
    }
}

// ---------------------------------------------------------------------------
// Combine fp16 partials. Grid (32, B, 8). m already in log2 domain.
// ---------------------------------------------------------------------------
__global__ __launch_bounds__(256) void reduce_kernel(float* __restrict__ out) {
    const int mb = blockIdx.x, b = blockIdx.y;
    const int nc = (2 * mb + 2 + CBLK - 1) / CBLK;
    const int tid = threadIdx.x;
    const int r = tid >> 1;
    const int col = blockIdx.z * 8 + (tid & 1) * 4;
    const size_t ubase = ((size_t)(b * 32 + mb)) * NCHUNK;

    float m[NCHUNK], wgt[NCHUNK];
    float mstar = -1e30f;
    #pragma unroll
    for (int c = 0; c < NCHUNK; ++c) {
        if (c < nc) {
            m[c] = g_pm[(ubase + c) * QBLK + r];
            mstar = fmaxf(mstar, m[c]);
        }
    }
    float lsum = 0.f;
    #pragma unroll
    for (int c = 0; c < NCHUNK; ++c) {
        if (c < nc) {
            wgt[c] = exp2f(m[c] - mstar);
            lsum += wgt[c] * g_pl[(ubase + c) * QBLK + r];
        }
    }
    float inv = 1.f / lsum;

    float4 o = make_float4(0.f, 0.f, 0.f, 0.f);
    #pragma unroll
    for (int c = 0; c < NCHUNK; ++c) {
        if (c < nc) {
            uint2 pk = *(const uint2*)&g_po[((ubase + c) * QBLK + r) * HS + col];
            float2 p01 = __half22float2(*(__half2*)&pk.x);
            float2 p23 = __half22float2(*(__half2*)&pk.y);
            o.x += wgt[c] * p01.x;
            o.y += wgt[c] * p01.y;
            o.z += wgt[c] * p23.x;
            o.w += wgt[c] * p23.y;
        }
    }
    *(float4*)&out[((size_t)b * T_DIM + mb * QBLK + r) * HS + col] =
        make_float4(o.x * inv, o.y * inv, o.z * inv, o.w * inv);
}

extern "C" void kernel_launch(void* const* d_in, const int* in_sizes, int n_in,
                              void* d_out, int out_size) {
    const float* x = (const float*)d_in[0];
    const float* Wk = (const float*)d_in[1];
    const float* Wv = (const float*)d_in[2];
    float* out = (float*)d_out;

    const int smemProj = 4 * 64 * PB * sizeof(uint16_t);  // 36864
    const int smemAttn = NSTAGE * BUFBYTES;               // 55296
    cudaFuncSetAttribute(proj_kernel, cudaFuncAttributeMaxDynamicSharedMemorySize, smemProj);
    cudaFuncSetAttribute(attn_kernel, cudaFuncAttributeMaxDynamicSharedMemorySize, smemAttn);

    wconv_kernel<<<HS * D_DIM / 512, 256>>>(Wk, Wv);
    proj_kernel<<<(B_DIM * T_DIM) / 64, 128, smemProj>>>(x);
    attn_kernel<<<dim3(32, NCHUNK, B_DIM), 128, smemAttn>>>();
    reduce_kernel<<<dim3(32, B_DIM, 8), 256>>>(out);
}

// round 15
// speedup vs baseline: 1.4891x; 1.0699x over previous
#include <cuda_runtime.h>
#include <cuda_fp16.h>
#include <cstdint>

#define B_DIM 4
#define T_DIM 4096
#define D_DIM 1024
#define HS 64
#define PB 72      // fp16 pitch: conflict-free frag + ldmatrix loads
#define QBLK 128   // q rows per attn CTA
#define NCHUNK 4   // max kv chunks per q-block
#define CBLK 16    // kv blocks (of 64 keys) per chunk

// Projected tensors (fp16). g_qh is pre-scaled by CSC (softmax scale in log2).
__device__ __align__(16) uint16_t g_kh[B_DIM * T_DIM * HS];
__device__ __align__(16) uint16_t g_qh[B_DIM * T_DIM * HS];
__device__ __align__(16) uint16_t g_vth[B_DIM * HS * T_DIM];  // QV^T [b][h][t]

// Preconverted weights (fp16 hi only)
__device__ __align__(16) uint16_t g_wkh[HS * D_DIM];
__device__ __align__(16) uint16_t g_wvh[HS * D_DIM];

// Split-KV partials
__device__ __align__(16) uint16_t g_po[B_DIM * 32 * NCHUNK * QBLK * HS];  // fp16
__device__ float g_pm[B_DIM * 32 * NCHUNK * QBLK];   // in scaled-log2 domain
__device__ float g_pl[B_DIM * 32 * NCHUNK * QBLK];

#define CSC 0.1803368801111204f  // 0.125 * log2(e)

__device__ __forceinline__ uint32_t hpack(float a, float b) {
    __half2 hh = __floats2half2_rn(a, b);
    return *(uint32_t*)&hh;
}
__device__ __forceinline__ void mma_f16(float* c, uint32_t a0, uint32_t a1,
                                        uint32_t a2, uint32_t a3,
                                        uint32_t b0, uint32_t b1) {
    asm volatile(
        "mma.sync.aligned.m16n8k16.row.col.f32.f16.f16.f32 "
        "{%0,%1,%2,%3}, {%4,%5,%6,%7}, {%8,%9}, {%0,%1,%2,%3};"
        : "+f"(c[0]), "+f"(c[1]), "+f"(c[2]), "+f"(c[3])
        : "r"(a0), "r"(a1), "r"(a2), "r"(a3), "r"(b0), "r"(b1));
}
__device__ __forceinline__ void ldsm4(uint32_t& r0, uint32_t& r1, uint32_t& r2,
                                      uint32_t& r3, uint32_t addr) {
    asm volatile(
        "ldmatrix.sync.aligned.m8n8.x4.shared.b16 {%0,%1,%2,%3}, [%4];"
        : "=r"(r0), "=r"(r1), "=r"(r2), "=r"(r3) : "r"(addr));
}
__device__ __forceinline__ void cpa16(uint32_t dst, const void* src) {
    asm volatile("cp.async.cg.shared.global [%0], [%1], 16;" :: "r"(dst), "l"(src));
}
#define LD32(arr, idx) (*(const uint32_t*)&(arr)[idx])

// ---------------------------------------------------------------------------
// One-time weight conversion fp32 -> fp16 (hi only)
// ---------------------------------------------------------------------------
__global__ __launch_bounds__(256) void wconv_kernel(const float* __restrict__ Wk,
                                                    const float* __restrict__ Wv) {
    int i = blockIdx.x * 512 + threadIdx.x * 2;
    *(uint32_t*)&g_wkh[i] = hpack(Wk[i], Wk[i + 1]);
    *(uint32_t*)&g_wvh[i] = hpack(Wv[i], Wv[i + 1]);
}

// ---------------------------------------------------------------------------
// Projection: 64-row CTAs, 128 thr, 3 CTAs/SM.
// k = xh@Wkh^T (1-MMA), qv = xh@Wvh^T (1-MMA). W frags via ldmatrix.
// ---------------------------------------------------------------------------
__global__ __launch_bounds__(128, 3) void proj_kernel(const float* __restrict__ x) {
    extern __shared__ __align__(16) uint16_t sm[];
    uint16_t* sXh = sm;
    const uint32_t smb = (uint32_t)__cvta_generic_to_shared(sm);
    const uint32_t AB = 64 * PB * 2;

    const int tid = threadIdx.x;
    const int w = tid >> 5, lane = tid & 31, g = lane >> 2, t = lane & 3;
    const int RB = blockIdx.x * 64;
    const int m0 = w * 16;

    // ldmatrix per-lane byte offset within a W tile
    const uint32_t laneW =
        (uint32_t)(((lane >> 4) * 8 * PB) + ((lane & 7) * PB) + (((lane >> 3) & 1) * 8)) * 2;

    float accK[8][4] = {};
    float accV[8][4] = {};

    for (int d0 = 0; d0 < D_DIM; d0 += 64) {
        __syncthreads();
        // W tiles via cp.async: 2 arrays x 512 16B-chunks
        #pragma unroll
        for (int l = 0; l < 4; ++l) {
            int id = tid + l * 128;
            int r = id >> 3, c8 = (id & 7) * 8;
            uint32_t soff = (uint32_t)(r * PB + c8) * 2;
            size_t go = (size_t)r * D_DIM + d0 + c8;
            cpa16(smb + AB + soff, &g_wkh[go]);
            cpa16(smb + 2 * AB + soff, &g_wvh[go]);
        }
        asm volatile("cp.async.commit_group;");
        // x tile: fp32 -> fp16 (hi only)
        #pragma unroll
        for (int l = 0; l < 8; ++l) {
            int idx = tid + l * 128;
            int r = idx >> 4, c = (idx & 15) * 4;
            float4 fx = *(const float4*)&x[(size_t)(RB + r) * D_DIM + d0 + c];
            *(uint32_t*)&sXh[r * PB + c] = hpack(fx.x, fx.y);
            *(uint32_t*)&sXh[r * PB + c + 2] = hpack(fx.z, fx.w);
        }
        asm volatile("cp.async.wait_group 0;" ::: "memory");
        __syncthreads();

        const uint32_t kWBase = smb + AB + laneW;
        const uint32_t vWBase = smb + 2 * AB + laneW;

        #pragma unroll
        for (int k0 = 0; k0 < 64; k0 += 16) {
            int ra = (m0 + g) * PB + k0 + 2 * t;
            uint32_t ah0 = LD32(sXh, ra);
            uint32_t ah1 = LD32(sXh, ra + 8 * PB);
            uint32_t ah2 = LD32(sXh, ra + 8);
            uint32_t ah3 = LD32(sXh, ra + 8 * PB + 8);
            #pragma unroll
            for (int jp = 0; jp < 4; ++jp) {
                uint32_t koff = (uint32_t)((jp * 16 * PB + k0) * 2);
                uint32_t k0r, k1r, k2r, k3r;
                ldsm4(k0r, k1r, k2r, k3r, kWBase + koff);
                mma_f16(accK[2 * jp], ah0, ah1, ah2, ah3, k0r, k1r);
                mma_f16(accK[2 * jp + 1], ah0, ah1, ah2, ah3, k2r, k3r);
                uint32_t v0r, v1r, v2r, v3r;
                ldsm4(v0r, v1r, v2r, v3r, vWBase + koff);
                mma_f16(accV[2 * jp], ah0, ah1, ah2, ah3, v0r, v1r);
                mma_f16(accV[2 * jp + 1], ah0, ah1, ah2, ah3, v2r, v3r);
            }
        }
    }

    const int row0 = RB + m0 + g;
    const int batch = row0 / T_DIM;
    const int tl0 = row0 % T_DIM;

    #pragma unroll
    for (int j = 0; j < 8; ++j) {
        int col = 8 * j + 2 * t;
        *(uint32_t*)&g_kh[(size_t)row0 * HS + col] = hpack(accK[j][0], accK[j][1]);
        *(uint32_t*)&g_kh[(size_t)(row0 + 8) * HS + col] = hpack(accK[j][2], accK[j][3]);
        *(uint32_t*)&g_qh[(size_t)row0 * HS + col] =
            hpack(accV[j][0] * CSC, accV[j][1] * CSC);
        *(uint32_t*)&g_qh[(size_t)(row0 + 8) * HS + col] =
            hpack(accV[j][2] * CSC, accV[j][3] * CSC);
        #pragma unroll
        for (int q = 0; q < 4; ++q) {
            float v = accV[j][q];
            int cc = col + (q & 1);
            int tt = tl0 + (q >> 1) * 8;
            __half hv = __float2half_rn(v);
            g_vth[((size_t)batch * HS + cc) * T_DIM + tt] = *(uint16_t*)&hv;
        }
    }
}

// ---------------------------------------------------------------------------
// Split-KV flash attention, QBLK=128, ldmatrix fragment loads.
// ---------------------------------------------------------------------------
#define ABYTES (64 * PB * 2)
#define BUFBYTES (2 * ABYTES)   // Kh, Vth
#define AU16 (64 * PB)
#define NSTAGE 3

__global__ __launch_bounds__(128, 2) void attn_kernel() {
    const int mblk = 31 - blockIdx.x;          // longest-first
    const int kbLast = 2 * mblk + 1;
    const int kb0 = blockIdx.y * CBLK;
    if (kb0 > kbLast) return;
    const int kb1 = min(kb0 + CBLK - 1, kbLast);
    const int b = blockIdx.z;
    const int unit = (b * 32 + mblk) * NCHUNK + blockIdx.y;

    extern __shared__ __align__(16) uint16_t sm[];
    const uint32_t smb = (uint32_t)__cvta_generic_to_shared(sm);

    const int tid = threadIdx.x;
    const int w = tid >> 5, lane = tid & 31, g = lane >> 2, t = lane & 3;
    const int qRow = mblk * QBLK;
    const int m0 = w * 32;
    const int lr = tid >> 3;
    const int lc = (tid & 7) * 8;

    const uint32_t laneK =
        (uint32_t)(((lane >> 4) * 8 * PB) + ((lane & 7) * PB) + (((lane >> 3) & 1) * 8)) * 2;

    // Q A-fragments (single fp16, pre-scaled), two row tiles
    uint32_t q[2][4][4];
    {
        const uint16_t* Qh = g_qh + (size_t)b * T_DIM * HS;
        #pragma unroll
        for (int tt = 0; tt < 2; ++tt) {
            int base = (qRow + m0 + tt * 16 + g) * HS + 2 * t;
            #pragma unroll
            for (int kk = 0; kk < 4; ++kk) {
                int o = base + kk * 16;
                q[tt][kk][0] = LD32(Qh, o);
                q[tt][kk][1] = LD32(Qh, o + 8 * HS);
                q[tt][kk][2] = LD32(Qh, o + 8);
                q[tt][kk][3] = LD32(Qh, o + 8 * HS + 8);
            }
        }
    }

    auto issue_tile = [&](int kb) {
        uint32_t base = smb + (uint32_t)(kb % NSTAGE) * BUFBYTES;
        #pragma unroll
        for (int l = 0; l < 4; ++l) {
            int r = lr + l * 16;
            uint32_t soff = (uint32_t)(r * PB + lc) * 2;
            size_t gk = ((size_t)b * T_DIM + kb * 64 + r) * HS + lc;
            cpa16(base + soff, &g_kh[gk]);
            size_t gv = ((size_t)b * HS + r) * T_DIM + kb * 64 + lc;
            cpa16(base + ABYTES + soff, &g_vth[gv]);
        }
        asm volatile("cp.async.commit_group;");
    };

    issue_tile(kb0);
    if (kb0 + 1 <= kb1) issue_tile(kb0 + 1);

    float acc[2][8][4] = {};
    float mrow[4] = {-1e30f, -1e30f, -1e30f, -1e30f};
    float lrow[4] = {0.f, 0.f, 0.f, 0.f};

    for (int kb = kb0; kb <= kb1; ++kb) {
        if (kb < kb1) {
            asm volatile("cp.async.wait_group 1;" ::: "memory");
        } else {
            asm volatile("cp.async.wait_group 0;" ::: "memory");
        }
        __syncthreads();
        if (kb + 2 <= kb1) issue_tile(kb + 2);

        const uint32_t kBase = smb + (uint32_t)(kb % NSTAGE) * BUFBYTES + laneK;
        const uint32_t vBase = kBase + ABYTES;

        // S = Q @ K^T, K fragments via ldmatrix.x4 (2 j per call)
        float s[2][8][4] = {};
        #pragma unroll
        for (int kk = 0; kk < 4; ++kk) {
            #pragma unroll
            for (int jp = 0; jp < 4; ++jp) {
                uint32_t b0, b1, b2, b3;
                ldsm4(b0, b1, b2, b3,
                      kBase + (uint32_t)((jp * 16 * PB + kk * 16) * 2));
                mma_f16(s[0][2 * jp], q[0][kk][0], q[0][kk][1], q[0][kk][2], q[0][kk][3], b0, b1);
                mma_f16(s[1][2 * jp], q[1][kk][0], q[1][kk][1], q[1][kk][2], q[1][kk][3], b0, b1);
                mma_f16(s[0][2 * jp + 1], q[0][kk][0], q[0][kk][1], q[0][kk][2], q[0][kk][3], b2, b3);
                mma_f16(s[1][2 * jp + 1], q[1][kk][0], q[1][kk][1], q[1][kk][2], q[1][kk][3], b2, b3);
            }
        }

        // causal mask: only last two kv blocks overlap the diagonal
        if (kb >= 2 * mblk) {
            const int off = qRow - kb * 64;
            #pragma unroll
            for (int tt = 0; tt < 2; ++tt) {
                int r0l = m0 + tt * 16 + g + off, r1l = r0l + 8;
                #pragma unroll
                for (int j = 0; j < 8; ++j) {
                    int c0 = 8 * j + 2 * t, c1 = c0 + 1;
                    if (c0 > r0l) s[tt][j][0] = -1e30f;
                    if (c1 > r0l) s[tt][j][1] = -1e30f;
                    if (c0 > r1l) s[tt][j][2] = -1e30f;
                    if (c1 > r1l) s[tt][j][3] = -1e30f;
                }
            }
        }

        // online softmax (scores already in log2 domain)
        #pragma unroll
        for (int tt = 0; tt < 2; ++tt) {
            float mx0 = -1e30f, mx1 = -1e30f;
            #pragma unroll
            for (int j = 0; j < 8; ++j) {
                mx0 = fmaxf(mx0, fmaxf(s[tt][j][0], s[tt][j][1]));
                mx1 = fmaxf(mx1, fmaxf(s[tt][j][2], s[tt][j][3]));
            }
            mx0 = fmaxf(mx0, __shfl_xor_sync(0xffffffffu, mx0, 1));
            mx0 = fmaxf(mx0, __shfl_xor_sync(0xffffffffu, mx0, 2));
            mx1 = fmaxf(mx1, __shfl_xor_sync(0xffffffffu, mx1, 1));
            mx1 = fmaxf(mx1, __shfl_xor_sync(0xffffffffu, mx1, 2));
            float mn0 = fmaxf(mrow[tt * 2], mx0), mn1 = fmaxf(mrow[tt * 2 + 1], mx1);
            float cr0 = exp2f(mrow[tt * 2] - mn0);
            float cr1 = exp2f(mrow[tt * 2 + 1] - mn1);
            float sum0 = 0.f, sum1 = 0.f;
            #pragma unroll
            for (int j = 0; j < 8; ++j) {
                s[tt][j][0] = exp2f(s[tt][j][0] - mn0);
                s[tt][j][1] = exp2f(s[tt][j][1] - mn0);
                s[tt][j][2] = exp2f(s[tt][j][2] - mn1);
                s[tt][j][3] = exp2f(s[tt][j][3] - mn1);
                sum0 += s[tt][j][0] + s[tt][j][1];
                sum1 += s[tt][j][2] + s[tt][j][3];
            }
            sum0 += __shfl_xor_sync(0xffffffffu, sum0, 1);
            sum0 += __shfl_xor_sync(0xffffffffu, sum0, 2);
            sum1 += __shfl_xor_sync(0xffffffffu, sum1, 1);
            sum1 += __shfl_xor_sync(0xffffffffu, sum1, 2);
            lrow[tt * 2] = lrow[tt * 2] * cr0 + sum0;
            lrow[tt * 2 + 1] = lrow[tt * 2 + 1] * cr1 + sum1;
            mrow[tt * 2] = mn0;
            mrow[tt * 2 + 1] = mn1;
            #pragma unroll
            for (int j = 0; j < 8; ++j) {
                acc[tt][j][0] *= cr0;
                acc[tt][j][1] *= cr0;
                acc[tt][j][2] *= cr1;
                acc[tt][j][3] *= cr1;
            }
        }

        // P (hi) x V, V fragments via ldmatrix.x4
        #pragma unroll
        for (int kk = 0; kk < 4; ++kk) {
            uint32_t ph[2][4];
            #pragma unroll
            for (int tt = 0; tt < 2; ++tt) {
                float* pA = s[tt][2 * kk];
                float* pB = s[tt][2 * kk + 1];
                ph[tt][0] = hpack(pA[0], pA[1]);
                ph[tt][1] = hpack(pA[2], pA[3]);
                ph[tt][2] = hpack(pB[0], pB[1]);
                ph[tt][3] = hpack(pB[2], pB[3]);
            }
            #pragma unroll
            for (int jp = 0; jp < 4; ++jp) {
                uint32_t v0, v1, v2, v3;
                ldsm4(v0, v1, v2, v3,
                      vBase + (uint32_t)((jp * 16 * PB + kk * 16) * 2));
                mma_f16(acc[0][2 * jp], ph[0][0], ph[0][1], ph[0][2], ph[0][3], v0, v1);
                mma_f16(acc[1][2 * jp], ph[1][0], ph[1][1], ph[1][2], ph[1][3], v0, v1);
                mma_f16(acc[0][2 * jp + 1], ph[0][0], ph[0][1], ph[0][2], ph[0][3], v2, v3);
                mma_f16(acc[1][2 * jp + 1], ph[1][0], ph[1][1], ph[1][2], ph[1][3], v2, v3);
            }
        }
    }

    // write partials (O as fp16; m in scaled-log2 domain)
    if (t == 0) {
        #pragma unroll
        for (int tt = 0; tt < 2; ++tt) {
            int r = m0 + tt * 16 + g;
            g_pm[(size_t)unit * QBLK + r] = mrow[tt * 2];
            g_pm[(size_t)unit * QBLK + r + 8] = mrow[tt * 2 + 1];
            g_pl[(size_t)unit * QBLK + r] = lrow[tt * 2];
            g_pl[(size_t)unit * QBLK + r + 8] = lrow[tt * 2 + 1];
        }
    }
    #pragma unroll
    for (int tt = 0; tt < 2; ++tt) {
        int r = m0 + tt * 16 + g;
        #pragma unroll
        for (int j = 0; j < 8; ++j) {
            int col = 8 * j + 2 * t;
            size_t pbase = ((size_t)unit * QBLK + r) * HS + col;
            *(uint32_t*)&g_po[pbase] = hpack(acc[tt][j][0], acc[tt][j][1]);
            *(uint32_t*)&g_po[pbase + 8 * HS] = hpack(acc[tt][j][2], acc[tt][j][3]);
        }
    }
}

// ---------------------------------------------------------------------------
// Combine fp16 partials. Grid (32, B, 8). m already in log2 domain.
// ---------------------------------------------------------------------------
__global__ __launch_bounds__(256) void reduce_kernel(float* __restrict__ out) {
    const int mb = blockIdx.x, b = blockIdx.y;
    const int nc = (2 * mb + 2 + CBLK - 1) / CBLK;
    const int tid = threadIdx.x;
    const int r = tid >> 1;
    const int col = blockIdx.z * 8 + (tid & 1) * 4;
    const size_t ubase = ((size_t)(b * 32 + mb)) * NCHUNK;

    float m[NCHUNK], wgt[NCHUNK];
    float mstar = -1e30f;
    #pragma unroll
    for (int c = 0; c < NCHUNK; ++c) {
        if (c < nc) {
            m[c] = g_pm[(ubase + c) * QBLK + r];
            mstar = fmaxf(mstar, m[c]);
        }
    }
    float lsum = 0.f;
    #pragma unroll
    for (int c = 0; c < NCHUNK; ++c) {
        if (c < nc) {
            wgt[c] = exp2f(m[c] - mstar);
            lsum += wgt[c] * g_pl[(ubase + c) * QBLK + r];
        }
    }
    float inv = 1.f / lsum;

    float4 o = make_float4(0.f, 0.f, 0.f, 0.f);
    #pragma unroll
    for (int c = 0; c < NCHUNK; ++c) {
        if (c < nc) {
            uint2 pk = *(const uint2*)&g_po[((ubase + c) * QBLK + r) * HS + col];
            float2 p01 = __half22float2(*(__half2*)&pk.x);
            float2 p23 = __half22float2(*(__half2*)&pk.y);
            o.x += wgt[c] * p01.x;
            o.y += wgt[c] * p01.y;
            o.z += wgt[c] * p23.x;
            o.w += wgt[c] * p23.y;
        }
    }
    *(float4*)&out[((size_t)b * T_DIM + mb * QBLK + r) * HS + col] =
        make_float4(o.x * inv, o.y * inv, o.z * inv, o.w * inv);
}

extern "C" void kernel_launch(void* const* d_in, const int* in_sizes, int n_in,
                              void* d_out, int out_size) {
    const float* x = (const float*)d_in[0];
    const float* Wk = (const float*)d_in[1];
    const float* Wv = (const float*)d_in[2];
    float* out = (float*)d_out;

    const int smemProj = 3 * 64 * PB * sizeof(uint16_t);  // 27648
    const int smemAttn = NSTAGE * BUFBYTES;               // 55296
    cudaFuncSetAttribute(proj_kernel, cudaFuncAttributeMaxDynamicSharedMemorySize, smemProj);
    cudaFuncSetAttribute(attn_kernel, cudaFuncAttributeMaxDynamicSharedMemorySize, smemAttn);

    wconv_kernel<<<HS * D_DIM / 512, 256>>>(Wk, Wv);
    proj_kernel<<<(B_DIM * T_DIM) / 64, 128, smemProj>>>(x);
    attn_kernel<<<dim3(32, NCHUNK, B_DIM), 128, smemAttn>>>();
    reduce_kernel<<<dim3(32, B_DIM, 8), 256>>>(out);
}

// round 16
// speedup vs baseline: 1.5055x; 1.0110x over previous
#include <cuda_runtime.h>
#include <cuda_fp16.h>
#include <cstdint>

#define B_DIM 4
#define T_DIM 4096
#define D_DIM 1024
#define HS 64
#define PB 72      // fp16 pitch: conflict-free frag + ldmatrix loads
#define QBLK 128   // q rows per attn CTA
#define NCHUNK 4   // max kv chunks per q-block
#define CBLK 16    // kv blocks (of 64 keys) per chunk

// Projected tensors (fp16). g_qh is pre-scaled by CSC (softmax scale in log2).
__device__ __align__(16) uint16_t g_kh[B_DIM * T_DIM * HS];
__device__ __align__(16) uint16_t g_qh[B_DIM * T_DIM * HS];
__device__ __align__(16) uint16_t g_vth[B_DIM * HS * T_DIM];  // QV^T [b][h][t]

// Preconverted weights (fp16 hi only)
__device__ __align__(16) uint16_t g_wkh[HS * D_DIM];
__device__ __align__(16) uint16_t g_wvh[HS * D_DIM];

// Split-KV partials
__device__ __align__(16) uint16_t g_po[B_DIM * 32 * NCHUNK * QBLK * HS];  // fp16
__device__ float g_pm[B_DIM * 32 * NCHUNK * QBLK];   // in scaled-log2 domain
__device__ float g_pl[B_DIM * 32 * NCHUNK * QBLK];

#define CSC 0.1803368801111204f  // 0.125 * log2(e)

__device__ __forceinline__ uint32_t hpack(float a, float b) {
    __half2 hh = __floats2half2_rn(a, b);
    return *(uint32_t*)&hh;
}
__device__ __forceinline__ uint32_t h2exp2(uint32_t v) {
    uint32_t r;
    asm("ex2.approx.f16x2 %0, %1;" : "=r"(r) : "r"(v));
    return r;
}
__device__ __forceinline__ void mma_f16(float* c, uint32_t a0, uint32_t a1,
                                        uint32_t a2, uint32_t a3,
                                        uint32_t b0, uint32_t b1) {
    asm volatile(
        "mma.sync.aligned.m16n8k16.row.col.f32.f16.f16.f32 "
        "{%0,%1,%2,%3}, {%4,%5,%6,%7}, {%8,%9}, {%0,%1,%2,%3};"
        : "+f"(c[0]), "+f"(c[1]), "+f"(c[2]), "+f"(c[3])
        : "r"(a0), "r"(a1), "r"(a2), "r"(a3), "r"(b0), "r"(b1));
}
__device__ __forceinline__ void ldsm4(uint32_t& r0, uint32_t& r1, uint32_t& r2,
                                      uint32_t& r3, uint32_t addr) {
    asm volatile(
        "ldmatrix.sync.aligned.m8n8.x4.shared.b16 {%0,%1,%2,%3}, [%4];"
        : "=r"(r0), "=r"(r1), "=r"(r2), "=r"(r3) : "r"(addr));
}
__device__ __forceinline__ void cpa16(uint32_t dst, const void* src) {
    asm volatile("cp.async.cg.shared.global [%0], [%1], 16;" :: "r"(dst), "l"(src));
}
#define LD32(arr, idx) (*(const uint32_t*)&(arr)[idx])

// ---------------------------------------------------------------------------
// One-time weight conversion fp32 -> fp16 (hi only)
// ---------------------------------------------------------------------------
__global__ __launch_bounds__(256) void wconv_kernel(const float* __restrict__ Wk,
                                                    const float* __restrict__ Wv) {
    int i = blockIdx.x * 512 + threadIdx.x * 2;
    *(uint32_t*)&g_wkh[i] = hpack(Wk[i], Wk[i + 1]);
    *(uint32_t*)&g_wvh[i] = hpack(Wv[i], Wv[i + 1]);
}

// ---------------------------------------------------------------------------
// Projection: 64-row CTAs, 128 thr, 3 CTAs/SM.
// k = xh@Wkh^T (1-MMA), qv = xh@Wvh^T (1-MMA). W frags via ldmatrix.
// ---------------------------------------------------------------------------
__global__ __launch_bounds__(128, 3) void proj_kernel(const float* __restrict__ x) {
    extern __shared__ __align__(16) uint16_t sm[];
    uint16_t* sXh = sm;
    const uint32_t smb = (uint32_t)__cvta_generic_to_shared(sm);
    const uint32_t AB = 64 * PB * 2;

    const int tid = threadIdx.x;
    const int w = tid >> 5, lane = tid & 31, g = lane >> 2, t = lane & 3;
    const int RB = blockIdx.x * 64;
    const int m0 = w * 16;

    const uint32_t laneW =
        (uint32_t)(((lane >> 4) * 8 * PB) + ((lane & 7) * PB) + (((lane >> 3) & 1) * 8)) * 2;

    float accK[8][4] = {};
    float accV[8][4] = {};

    for (int d0 = 0; d0 < D_DIM; d0 += 64) {
        __syncthreads();
        #pragma unroll
        for (int l = 0; l < 4; ++l) {
            int id = tid + l * 128;
            int r = id >> 3, c8 = (id & 7) * 8;
            uint32_t soff = (uint32_t)(r * PB + c8) * 2;
            size_t go = (size_t)r * D_DIM + d0 + c8;
            cpa16(smb + AB + soff, &g_wkh[go]);
            cpa16(smb + 2 * AB + soff, &g_wvh[go]);
        }
        asm volatile("cp.async.commit_group;");
        #pragma unroll
        for (int l = 0; l < 8; ++l) {
            int idx = tid + l * 128;
            int r = idx >> 4, c = (idx & 15) * 4;
            float4 fx = *(const float4*)&x[(size_t)(RB + r) * D_DIM + d0 + c];
            *(uint32_t*)&sXh[r * PB + c] = hpack(fx.x, fx.y);
            *(uint32_t*)&sXh[r * PB + c + 2] = hpack(fx.z, fx.w);
        }
        asm volatile("cp.async.wait_group 0;" ::: "memory");
        __syncthreads();

        const uint32_t kWBase = smb + AB + laneW;
        const uint32_t vWBase = smb + 2 * AB + laneW;

        #pragma unroll
        for (int k0 = 0; k0 < 64; k0 += 16) {
            int ra = (m0 + g) * PB + k0 + 2 * t;
            uint32_t ah0 = LD32(sXh, ra);
            uint32_t ah1 = LD32(sXh, ra + 8 * PB);
            uint32_t ah2 = LD32(sXh, ra + 8);
            uint32_t ah3 = LD32(sXh, ra + 8 * PB + 8);
            #pragma unroll
            for (int jp = 0; jp < 4; ++jp) {
                uint32_t koff = (uint32_t)((jp * 16 * PB + k0) * 2);
                uint32_t k0r, k1r, k2r, k3r;
                ldsm4(k0r, k1r, k2r, k3r, kWBase + koff);
                mma_f16(accK[2 * jp], ah0, ah1, ah2, ah3, k0r, k1r);
                mma_f16(accK[2 * jp + 1], ah0, ah1, ah2, ah3, k2r, k3r);
                uint32_t v0r, v1r, v2r, v3r;
                ldsm4(v0r, v1r, v2r, v3r, vWBase + koff);
                mma_f16(accV[2 * jp], ah0, ah1, ah2, ah3, v0r, v1r);
                mma_f16(accV[2 * jp + 1], ah0, ah1, ah2, ah3, v2r, v3r);
            }
        }
    }

    const int row0 = RB + m0 + g;
    const int batch = row0 / T_DIM;
    const int tl0 = row0 % T_DIM;

    #pragma unroll
    for (int j = 0; j < 8; ++j) {
        int col = 8 * j + 2 * t;
        *(uint32_t*)&g_kh[(size_t)row0 * HS + col] = hpack(accK[j][0], accK[j][1]);
        *(uint32_t*)&g_kh[(size_t)(row0 + 8) * HS + col] = hpack(accK[j][2], accK[j][3]);
        *(uint32_t*)&g_qh[(size_t)row0 * HS + col] =
            hpack(accV[j][0] * CSC, accV[j][1] * CSC);
        *(uint32_t*)&g_qh[(size_t)(row0 + 8) * HS + col] =
            hpack(accV[j][2] * CSC, accV[j][3] * CSC);
        #pragma unroll
        for (int q = 0; q < 4; ++q) {
            float v = accV[j][q];
            int cc = col + (q & 1);
            int tt = tl0 + (q >> 1) * 8;
            __half hv = __float2half_rn(v);
            g_vth[((size_t)batch * HS + cc) * T_DIM + tt] = *(uint16_t*)&hv;
        }
    }
}

// ---------------------------------------------------------------------------
// Split-KV flash attention, QBLK=128, fp16x2 softmax exp.
// ---------------------------------------------------------------------------
#define ABYTES (64 * PB * 2)
#define BUFBYTES (2 * ABYTES)   // Kh, Vth
#define AU16 (64 * PB)
#define NSTAGE 3

__global__ __launch_bounds__(128, 2) void attn_kernel() {
    const int mblk = 31 - blockIdx.x;          // longest-first
    const int kbLast = 2 * mblk + 1;
    const int kb0 = blockIdx.y * CBLK;
    if (kb0 > kbLast) return;
    const int kb1 = min(kb0 + CBLK - 1, kbLast);
    const int b = blockIdx.z;
    const int unit = (b * 32 + mblk) * NCHUNK + blockIdx.y;

    extern __shared__ __align__(16) uint16_t sm[];
    const uint32_t smb = (uint32_t)__cvta_generic_to_shared(sm);

    const int tid = threadIdx.x;
    const int w = tid >> 5, lane = tid & 31, g = lane >> 2, t = lane & 3;
    const int qRow = mblk * QBLK;
    const int m0 = w * 32;
    const int lr = tid >> 3;
    const int lc = (tid & 7) * 8;

    const uint32_t laneK =
        (uint32_t)(((lane >> 4) * 8 * PB) + ((lane & 7) * PB) + (((lane >> 3) & 1) * 8)) * 2;

    // Q A-fragments (single fp16, pre-scaled), two row tiles
    uint32_t q[2][4][4];
    {
        const uint16_t* Qh = g_qh + (size_t)b * T_DIM * HS;
        #pragma unroll
        for (int tt = 0; tt < 2; ++tt) {
            int base = (qRow + m0 + tt * 16 + g) * HS + 2 * t;
            #pragma unroll
            for (int kk = 0; kk < 4; ++kk) {
                int o = base + kk * 16;
                q[tt][kk][0] = LD32(Qh, o);
                q[tt][kk][1] = LD32(Qh, o + 8 * HS);
                q[tt][kk][2] = LD32(Qh, o + 8);
                q[tt][kk][3] = LD32(Qh, o + 8 * HS + 8);
            }
        }
    }

    auto issue_tile = [&](int kb) {
        uint32_t base = smb + (uint32_t)(kb % NSTAGE) * BUFBYTES;
        #pragma unroll
        for (int l = 0; l < 4; ++l) {
            int r = lr + l * 16;
            uint32_t soff = (uint32_t)(r * PB + lc) * 2;
            size_t gk = ((size_t)b * T_DIM + kb * 64 + r) * HS + lc;
            cpa16(base + soff, &g_kh[gk]);
            size_t gv = ((size_t)b * HS + r) * T_DIM + kb * 64 + lc;
            cpa16(base + ABYTES + soff, &g_vth[gv]);
        }
        asm volatile("cp.async.commit_group;");
    };

    issue_tile(kb0);
    if (kb0 + 1 <= kb1) issue_tile(kb0 + 1);

    float acc[2][8][4] = {};
    float mrow[4] = {-1e30f, -1e30f, -1e30f, -1e30f};
    float lrow[4] = {0.f, 0.f, 0.f, 0.f};

    for (int kb = kb0; kb <= kb1; ++kb) {
        if (kb < kb1) {
            asm volatile("cp.async.wait_group 1;" ::: "memory");
        } else {
            asm volatile("cp.async.wait_group 0;" ::: "memory");
        }
        __syncthreads();
        if (kb + 2 <= kb1) issue_tile(kb + 2);

        const uint32_t kBase = smb + (uint32_t)(kb % NSTAGE) * BUFBYTES + laneK;
        const uint32_t vBase = kBase + ABYTES;

        // S = Q @ K^T, K fragments via ldmatrix.x4 (2 j per call)
        float s[2][8][4] = {};
        #pragma unroll
        for (int kk = 0; kk < 4; ++kk) {
            #pragma unroll
            for (int jp = 0; jp < 4; ++jp) {
                uint32_t b0, b1, b2, b3;
                ldsm4(b0, b1, b2, b3,
                      kBase + (uint32_t)((jp * 16 * PB + kk * 16) * 2));
                mma_f16(s[0][2 * jp], q[0][kk][0], q[0][kk][1], q[0][kk][2], q[0][kk][3], b0, b1);
                mma_f16(s[1][2 * jp], q[1][kk][0], q[1][kk][1], q[1][kk][2], q[1][kk][3], b0, b1);
                mma_f16(s[0][2 * jp + 1], q[0][kk][0], q[0][kk][1], q[0][kk][2], q[0][kk][3], b2, b3);
                mma_f16(s[1][2 * jp + 1], q[1][kk][0], q[1][kk][1], q[1][kk][2], q[1][kk][3], b2, b3);
            }
        }

        // causal mask: only last two kv blocks overlap the diagonal
        if (kb >= 2 * mblk) {
            const int off = qRow - kb * 64;
            #pragma unroll
            for (int tt = 0; tt < 2; ++tt) {
                int r0l = m0 + tt * 16 + g + off, r1l = r0l + 8;
                #pragma unroll
                for (int j = 0; j < 8; ++j) {
                    int c0 = 8 * j + 2 * t, c1 = c0 + 1;
                    if (c0 > r0l) s[tt][j][0] = -1e30f;
                    if (c1 > r0l) s[tt][j][1] = -1e30f;
                    if (c0 > r1l) s[tt][j][2] = -1e30f;
                    if (c1 > r1l) s[tt][j][3] = -1e30f;
                }
            }
        }

        // online softmax with fp16x2 exp (scores in log2 domain).
        // P fragments come straight out of h2exp2.
        uint32_t pfrag[2][8][2];
        #pragma unroll
        for (int tt = 0; tt < 2; ++tt) {
            float mx0 = -1e30f, mx1 = -1e30f;
            #pragma unroll
            for (int j = 0; j < 8; ++j) {
                mx0 = fmaxf(mx0, fmaxf(s[tt][j][0], s[tt][j][1]));
                mx1 = fmaxf(mx1, fmaxf(s[tt][j][2], s[tt][j][3]));
            }
            mx0 = fmaxf(mx0, __shfl_xor_sync(0xffffffffu, mx0, 1));
            mx0 = fmaxf(mx0, __shfl_xor_sync(0xffffffffu, mx0, 2));
            mx1 = fmaxf(mx1, __shfl_xor_sync(0xffffffffu, mx1, 1));
            mx1 = fmaxf(mx1, __shfl_xor_sync(0xffffffffu, mx1, 2));
            float mn0 = fmaxf(mrow[tt * 2], mx0), mn1 = fmaxf(mrow[tt * 2 + 1], mx1);
            float cr0 = exp2f(mrow[tt * 2] - mn0);
            float cr1 = exp2f(mrow[tt * 2 + 1] - mn1);
            float sum0 = 0.f, sum1 = 0.f;
            #pragma unroll
            for (int j = 0; j < 8; ++j) {
                uint32_t e0 = h2exp2(hpack(s[tt][j][0] - mn0, s[tt][j][1] - mn0));
                uint32_t e1 = h2exp2(hpack(s[tt][j][2] - mn1, s[tt][j][3] - mn1));
                pfrag[tt][j][0] = e0;
                pfrag[tt][j][1] = e1;
                float2 f0 = __half22float2(*(__half2*)&e0);
                float2 f1 = __half22float2(*(__half2*)&e1);
                sum0 += f0.x + f0.y;
                sum1 += f1.x + f1.y;
            }
            sum0 += __shfl_xor_sync(0xffffffffu, sum0, 1);
            sum0 += __shfl_xor_sync(0xffffffffu, sum0, 2);
            sum1 += __shfl_xor_sync(0xffffffffu, sum1, 1);
            sum1 += __shfl_xor_sync(0xffffffffu, sum1, 2);
            lrow[tt * 2] = lrow[tt * 2] * cr0 + sum0;
            lrow[tt * 2 + 1] = lrow[tt * 2 + 1] * cr1 + sum1;
            mrow[tt * 2] = mn0;
            mrow[tt * 2 + 1] = mn1;
            #pragma unroll
            for (int j = 0; j < 8; ++j) {
                acc[tt][j][0] *= cr0;
                acc[tt][j][1] *= cr0;
                acc[tt][j][2] *= cr1;
                acc[tt][j][3] *= cr1;
            }
        }

        // P (packed fp16 from exp) x V, V fragments via ldmatrix.x4
        #pragma unroll
        for (int kk = 0; kk < 4; ++kk) {
            #pragma unroll
            for (int jp = 0; jp < 4; ++jp) {
                uint32_t v0, v1, v2, v3;
                ldsm4(v0, v1, v2, v3,
                      vBase + (uint32_t)((jp * 16 * PB + kk * 16) * 2));
                mma_f16(acc[0][2 * jp],
                        pfrag[0][2 * kk][0], pfrag[0][2 * kk][1],
                        pfrag[0][2 * kk + 1][0], pfrag[0][2 * kk + 1][1], v0, v1);
                mma_f16(acc[1][2 * jp],
                        pfrag[1][2 * kk][0], pfrag[1][2 * kk][1],
                        pfrag[1][2 * kk + 1][0], pfrag[1][2 * kk + 1][1], v0, v1);
                mma_f16(acc[0][2 * jp + 1],
                        pfrag[0][2 * kk][0], pfrag[0][2 * kk][1],
                        pfrag[0][2 * kk + 1][0], pfrag[0][2 * kk + 1][1], v2, v3);
                mma_f16(acc[1][2 * jp + 1],
                        pfrag[1][2 * kk][0], pfrag[1][2 * kk][1],
                        pfrag[1][2 * kk + 1][0], pfrag[1][2 * kk + 1][1], v2, v3);
            }
        }
    }

    // write partials (O as fp16; m in scaled-log2 domain)
    if (t == 0) {
        #pragma unroll
        for (int tt = 0; tt < 2; ++tt) {
            int r = m0 + tt * 16 + g;
            g_pm[(size_t)unit * QBLK + r] = mrow[tt * 2];
            g_pm[(size_t)unit * QBLK + r + 8] = mrow[tt * 2 + 1];
            g_pl[(size_t)unit * QBLK + r] = lrow[tt * 2];
            g_pl[(size_t)unit * QBLK + r + 8] = lrow[tt * 2 + 1];
        }
    }
    #pragma unroll
    for (int tt = 0; tt < 2; ++tt) {
        int r = m0 + tt * 16 + g;
        #pragma unroll
        for (int j = 0; j < 8; ++j) {
            int col = 8 * j + 2 * t;
            size_t pbase = ((size_t)unit * QBLK + r) * HS + col;
            *(uint32_t*)&g_po[pbase] = hpack(acc[tt][j][0], acc[tt][j][1]);
            *(uint32_t*)&g_po[pbase + 8 * HS] = hpack(acc[tt][j][2], acc[tt][j][3]);
        }
    }
}

// ---------------------------------------------------------------------------
// Combine fp16 partials. Grid (32, B, 8). m already in log2 domain.
// ---------------------------------------------------------------------------
__global__ __launch_bounds__(256) void reduce_kernel(float* __restrict__ out) {
    const int mb = blockIdx.x, b = blockIdx.y;
    const int nc = (2 * mb + 2 + CBLK - 1) / CBLK;
    const int tid = threadIdx.x;
    const int r = tid >> 1;
    const int col = blockIdx.z * 8 + (tid & 1) * 4;
    const size_t ubase = ((size_t)(b * 32 + mb)) * NCHUNK;

    float m[NCHUNK], wgt[NCHUNK];
    float mstar = -1e30f;
    #pragma unroll
    for (int c = 0; c < NCHUNK; ++c) {
        if (c < nc) {
            m[c] = g_pm[(ubase + c) * QBLK + r];
            mstar = fmaxf(mstar, m[c]);
        }
    }
    float lsum = 0.f;
    #pragma unroll
    for (int c = 0; c < NCHUNK; ++c) {
        if (c < nc) {
            wgt[c] = exp2f(m[c] - mstar);
            lsum += wgt[c] * g_pl[(ubase + c) * QBLK + r];
        }
    }
    float inv = 1.f / lsum;

    float4 o = make_float4(0.f, 0.f, 0.f, 0.f);
    #pragma unroll
    for (int c = 0; c < NCHUNK; ++c) {
        if (c < nc) {
            uint2 pk = *(const uint2*)&g_po[((ubase + c) * QBLK + r) * HS + col];
            float2 p01 = __half22float2(*(__half2*)&pk.x);
            float2 p23 = __half22float2(*(__half2*)&pk.y);
            o.x += wgt[c] * p01.x;
            o.y += wgt[c] * p01.y;
            o.z += wgt[c] * p23.x;
            o.w += wgt[c] * p23.y;
        }
    }
    *(float4*)&out[((size_t)b * T_DIM + mb * QBLK + r) * HS + col] =
        make_float4(o.x * inv, o.y * inv, o.z * inv, o.w * inv);
}

extern "C" void kernel_launch(void* const* d_in, const int* in_sizes, int n_in,
                              void* d_out, int out_size) {
    const float* x = (const float*)d_in[0];
    const float* Wk = (const float*)d_in[1];
    const float* Wv = (const float*)d_in[2];
    float* out = (float*)d_out;

    const int smemProj = 3 * 64 * PB * sizeof(uint16_t);  // 27648
    const int smemAttn = NSTAGE * BUFBYTES;               // 55296
    cudaFuncSetAttribute(proj_kernel, cudaFuncAttributeMaxDynamicSharedMemorySize, smemProj);
    cudaFuncSetAttribute(attn_kernel, cudaFuncAttributeMaxDynamicSharedMemorySize, smemAttn);

    wconv_kernel<<<HS * D_DIM / 512, 256>>>(Wk, Wv);
    proj_kernel<<<(B_DIM * T_DIM) / 64, 128, smemProj>>>(x);
    attn_kernel<<<dim3(32, NCHUNK, B_DIM), 128, smemAttn>>>();
    reduce_kernel<<<dim3(32, B_DIM, 8), 256>>>(out);
}

// round 17
// speedup vs baseline: 1.5486x; 1.0286x over previous
#include <cuda_runtime.h>
#include <cuda_fp16.h>
#include <cstdint>

#define B_DIM 4
#define T_DIM 4096
#define D_DIM 1024
#define HS 64
#define PB 72      // fp16 pitch: conflict-free frag + ldmatrix loads
#define QBLK 128   // q rows per attn CTA
#define NCHUNK 4   // max kv chunks per q-block
#define CBLK 16    // kv blocks (of 64 keys) per chunk

// Projected tensors (fp16). g_qh is pre-scaled by CSC (softmax scale in log2).
__device__ __align__(16) uint16_t g_kh[B_DIM * T_DIM * HS];
__device__ __align__(16) uint16_t g_qh[B_DIM * T_DIM * HS];
__device__ __align__(16) uint16_t g_vth[B_DIM * HS * T_DIM];  // QV^T [b][h][t]

// Preconverted weights (fp16 hi only)
__device__ __align__(16) uint16_t g_wkh[HS * D_DIM];
__device__ __align__(16) uint16_t g_wvh[HS * D_DIM];

// Split-KV partials
__device__ __align__(16) uint16_t g_po[B_DIM * 32 * NCHUNK * QBLK * HS];  // fp16
__device__ float g_pm[B_DIM * 32 * NCHUNK * QBLK];   // in scaled-log2 domain
__device__ float g_pl[B_DIM * 32 * NCHUNK * QBLK];

#define CSC 0.1803368801111204f  // 0.125 * log2(e)

__device__ __forceinline__ uint32_t hpack(float a, float b) {
    __half2 hh = __floats2half2_rn(a, b);
    return *(uint32_t*)&hh;
}
__device__ __forceinline__ uint32_t h2exp2(uint32_t v) {
    uint32_t r;
    asm("ex2.approx.f16x2 %0, %1;" : "=r"(r) : "r"(v));
    return r;
}
__device__ __forceinline__ void mma_f16(float* c, uint32_t a0, uint32_t a1,
                                        uint32_t a2, uint32_t a3,
                                        uint32_t b0, uint32_t b1) {
    asm volatile(
        "mma.sync.aligned.m16n8k16.row.col.f32.f16.f16.f32 "
        "{%0,%1,%2,%3}, {%4,%5,%6,%7}, {%8,%9}, {%0,%1,%2,%3};"
        : "+f"(c[0]), "+f"(c[1]), "+f"(c[2]), "+f"(c[3])
        : "r"(a0), "r"(a1), "r"(a2), "r"(a3), "r"(b0), "r"(b1));
}
__device__ __forceinline__ void ldsm4(uint32_t& r0, uint32_t& r1, uint32_t& r2,
                                      uint32_t& r3, uint32_t addr) {
    asm volatile(
        "ldmatrix.sync.aligned.m8n8.x4.shared.b16 {%0,%1,%2,%3}, [%4];"
        : "=r"(r0), "=r"(r1), "=r"(r2), "=r"(r3) : "r"(addr));
}
__device__ __forceinline__ void cpa16(uint32_t dst, const void* src) {
    asm volatile("cp.async.cg.shared.global [%0], [%1], 16;" :: "r"(dst), "l"(src));
}
#define LD32(arr, idx) (*(const uint32_t*)&(arr)[idx])

// ---------------------------------------------------------------------------
// One-time weight conversion fp32 -> fp16 (hi only)
// ---------------------------------------------------------------------------
__global__ __launch_bounds__(256) void wconv_kernel(const float* __restrict__ Wk,
                                                    const float* __restrict__ Wv) {
    int i = blockIdx.x * 512 + threadIdx.x * 2;
    *(uint32_t*)&g_wkh[i] = hpack(Wk[i], Wk[i + 1]);
    *(uint32_t*)&g_wvh[i] = hpack(Wv[i], Wv[i + 1]);
}

// ---------------------------------------------------------------------------
// Projection: 64-row CTAs, 128 thr, 3 CTAs/SM.
// k = xh@Wkh^T (1-MMA), qv = xh@Wvh^T (1-MMA). W frags via ldmatrix.
// ---------------------------------------------------------------------------
__global__ __launch_bounds__(128, 3) void proj_kernel(const float* __restrict__ x) {
    extern __shared__ __align__(16) uint16_t sm[];
    uint16_t* sXh = sm;
    const uint32_t smb = (uint32_t)__cvta_generic_to_shared(sm);
    const uint32_t AB = 64 * PB * 2;

    const int tid = threadIdx.x;
    const int w = tid >> 5, lane = tid & 31, g = lane >> 2, t = lane & 3;
    const int RB = blockIdx.x * 64;
    const int m0 = w * 16;

    const uint32_t laneW =
        (uint32_t)(((lane >> 4) * 8 * PB) + ((lane & 7) * PB) + (((lane >> 3) & 1) * 8)) * 2;

    float accK[8][4] = {};
    float accV[8][4] = {};

    for (int d0 = 0; d0 < D_DIM; d0 += 64) {
        __syncthreads();
        #pragma unroll
        for (int l = 0; l < 4; ++l) {
            int id = tid + l * 128;
            int r = id >> 3, c8 = (id & 7) * 8;
            uint32_t soff = (uint32_t)(r * PB + c8) * 2;
            size_t go = (size_t)r * D_DIM + d0 + c8;
            cpa16(smb + AB + soff, &g_wkh[go]);
            cpa16(smb + 2 * AB + soff, &g_wvh[go]);
        }
        asm volatile("cp.async.commit_group;");
        #pragma unroll
        for (int l = 0; l < 8; ++l) {
            int idx = tid + l * 128;
            int r = idx >> 4, c = (idx & 15) * 4;
            float4 fx = *(const float4*)&x[(size_t)(RB + r) * D_DIM + d0 + c];
            *(uint32_t*)&sXh[r * PB + c] = hpack(fx.x, fx.y);
            *(uint32_t*)&sXh[r * PB + c + 2] = hpack(fx.z, fx.w);
        }
        asm volatile("cp.async.wait_group 0;" ::: "memory");
        __syncthreads();

        const uint32_t kWBase = smb + AB + laneW;
        const uint32_t vWBase = smb + 2 * AB + laneW;

        #pragma unroll
        for (int k0 = 0; k0 < 64; k0 += 16) {
            int ra = (m0 + g) * PB + k0 + 2 * t;
            uint32_t ah0 = LD32(sXh, ra);
            uint32_t ah1 = LD32(sXh, ra + 8 * PB);
            uint32_t ah2 = LD32(sXh, ra + 8);
            uint32_t ah3 = LD32(sXh, ra + 8 * PB + 8);
            #pragma unroll
            for (int jp = 0; jp < 4; ++jp) {
                uint32_t koff = (uint32_t)((jp * 16 * PB + k0) * 2);
                uint32_t k0r, k1r, k2r, k3r;
                ldsm4(k0r, k1r, k2r, k3r, kWBase + koff);
                mma_f16(accK[2 * jp], ah0, ah1, ah2, ah3, k0r, k1r);
                mma_f16(accK[2 * jp + 1], ah0, ah1, ah2, ah3, k2r, k3r);
                uint32_t v0r, v1r, v2r, v3r;
                ldsm4(v0r, v1r, v2r, v3r, vWBase + koff);
                mma_f16(accV[2 * jp], ah0, ah1, ah2, ah3, v0r, v1r);
                mma_f16(accV[2 * jp + 1], ah0, ah1, ah2, ah3, v2r, v3r);
            }
        }
    }

    const int row0 = RB + m0 + g;
    const int batch = row0 / T_DIM;
    const int tl0 = row0 % T_DIM;

    #pragma unroll
    for (int j = 0; j < 8; ++j) {
        int col = 8 * j + 2 * t;
        *(uint32_t*)&g_kh[(size_t)row0 * HS + col] = hpack(accK[j][0], accK[j][1]);
        *(uint32_t*)&g_kh[(size_t)(row0 + 8) * HS + col] = hpack(accK[j][2], accK[j][3]);
        *(uint32_t*)&g_qh[(size_t)row0 * HS + col] =
            hpack(accV[j][0] * CSC, accV[j][1] * CSC);
        *(uint32_t*)&g_qh[(size_t)(row0 + 8) * HS + col] =
            hpack(accV[j][2] * CSC, accV[j][3] * CSC);
        #pragma unroll
        for (int q = 0; q < 4; ++q) {
            float v = accV[j][q];
            int cc = col + (q & 1);
            int tt = tl0 + (q >> 1) * 8;
            __half hv = __float2half_rn(v);
            g_vth[((size_t)batch * HS + cc) * T_DIM + tt] = *(uint16_t*)&hv;
        }
    }
}

// ---------------------------------------------------------------------------
// Split-KV flash attention, QBLK=128, fp16x2 softmax exp.
// Single-chunk q-blocks (mb<8) write normalized fp32 output directly.
// ---------------------------------------------------------------------------
#define ABYTES (64 * PB * 2)
#define BUFBYTES (2 * ABYTES)   // Kh, Vth
#define AU16 (64 * PB)
#define NSTAGE 3

__global__ __launch_bounds__(128, 2) void attn_kernel(float* __restrict__ out) {
    const int mblk = 31 - blockIdx.x;          // longest-first
    const int kbLast = 2 * mblk + 1;
    const int kb0 = blockIdx.y * CBLK;
    if (kb0 > kbLast) return;
    const int kb1 = min(kb0 + CBLK - 1, kbLast);
    const int b = blockIdx.z;
    const int unit = (b * 32 + mblk) * NCHUNK + blockIdx.y;
    const bool single = (kbLast < CBLK);       // whole q-block in one chunk

    extern __shared__ __align__(16) uint16_t sm[];
    const uint32_t smb = (uint32_t)__cvta_generic_to_shared(sm);

    const int tid = threadIdx.x;
    const int w = tid >> 5, lane = tid & 31, g = lane >> 2, t = lane & 3;
    const int qRow = mblk * QBLK;
    const int m0 = w * 32;
    const int lr = tid >> 3;
    const int lc = (tid & 7) * 8;

    const uint32_t laneK =
        (uint32_t)(((lane >> 4) * 8 * PB) + ((lane & 7) * PB) + (((lane >> 3) & 1) * 8)) * 2;

    // Q A-fragments (single fp16, pre-scaled), two row tiles
    uint32_t q[2][4][4];
    {
        const uint16_t* Qh = g_qh + (size_t)b * T_DIM * HS;
        #pragma unroll
        for (int tt = 0; tt < 2; ++tt) {
            int base = (qRow + m0 + tt * 16 + g) * HS + 2 * t;
            #pragma unroll
            for (int kk = 0; kk < 4; ++kk) {
                int o = base + kk * 16;
                q[tt][kk][0] = LD32(Qh, o);
                q[tt][kk][1] = LD32(Qh, o + 8 * HS);
                q[tt][kk][2] = LD32(Qh, o + 8);
                q[tt][kk][3] = LD32(Qh, o + 8 * HS + 8);
            }
        }
    }

    auto issue_tile = [&](int kb) {
        uint32_t base = smb + (uint32_t)(kb % NSTAGE) * BUFBYTES;
        #pragma unroll
        for (int l = 0; l < 4; ++l) {
            int r = lr + l * 16;
            uint32_t soff = (uint32_t)(r * PB + lc) * 2;
            size_t gk = ((size_t)b * T_DIM + kb * 64 + r) * HS + lc;
            cpa16(base + soff, &g_kh[gk]);
            size_t gv = ((size_t)b * HS + r) * T_DIM + kb * 64 + lc;
            cpa16(base + ABYTES + soff, &g_vth[gv]);
        }
        asm volatile("cp.async.commit_group;");
    };

    issue_tile(kb0);
    if (kb0 + 1 <= kb1) issue_tile(kb0 + 1);

    float acc[2][8][4] = {};
    float mrow[4] = {-1e30f, -1e30f, -1e30f, -1e30f};
    float lrow[4] = {0.f, 0.f, 0.f, 0.f};

    for (int kb = kb0; kb <= kb1; ++kb) {
        if (kb < kb1) {
            asm volatile("cp.async.wait_group 1;" ::: "memory");
        } else {
            asm volatile("cp.async.wait_group 0;" ::: "memory");
        }
        __syncthreads();
        if (kb + 2 <= kb1) issue_tile(kb + 2);

        const uint32_t kBase = smb + (uint32_t)(kb % NSTAGE) * BUFBYTES + laneK;
        const uint32_t vBase = kBase + ABYTES;

        // S = Q @ K^T, K fragments via ldmatrix.x4 (2 j per call)
        float s[2][8][4] = {};
        #pragma unroll
        for (int kk = 0; kk < 4; ++kk) {
            #pragma unroll
            for (int jp = 0; jp < 4; ++jp) {
                uint32_t b0, b1, b2, b3;
                ldsm4(b0, b1, b2, b3,
                      kBase + (uint32_t)((jp * 16 * PB + kk * 16) * 2));
                mma_f16(s[0][2 * jp], q[0][kk][0], q[0][kk][1], q[0][kk][2], q[0][kk][3], b0, b1);
                mma_f16(s[1][2 * jp], q[1][kk][0], q[1][kk][1], q[1][kk][2], q[1][kk][3], b0, b1);
                mma_f16(s[0][2 * jp + 1], q[0][kk][0], q[0][kk][1], q[0][kk][2], q[0][kk][3], b2, b3);
                mma_f16(s[1][2 * jp + 1], q[1][kk][0], q[1][kk][1], q[1][kk][2], q[1][kk][3], b2, b3);
            }
        }

        // causal mask: only last two kv blocks overlap the diagonal
        if (kb >= 2 * mblk) {
            const int off = qRow - kb * 64;
            #pragma unroll
            for (int tt = 0; tt < 2; ++tt) {
                int r0l = m0 + tt * 16 + g + off, r1l = r0l + 8;
                #pragma unroll
                for (int j = 0; j < 8; ++j) {
                    int c0 = 8 * j + 2 * t, c1 = c0 + 1;
                    if (c0 > r0l) s[tt][j][0] = -1e30f;
                    if (c1 > r0l) s[tt][j][1] = -1e30f;
                    if (c0 > r1l) s[tt][j][2] = -1e30f;
                    if (c1 > r1l) s[tt][j][3] = -1e30f;
                }
            }
        }

        // online softmax with fp16x2 exp (scores in log2 domain).
        uint32_t pfrag[2][8][2];
        #pragma unroll
        for (int tt = 0; tt < 2; ++tt) {
            float mx0 = -1e30f, mx1 = -1e30f;
            #pragma unroll
            for (int j = 0; j < 8; ++j) {
                mx0 = fmaxf(mx0, fmaxf(s[tt][j][0], s[tt][j][1]));
                mx1 = fmaxf(mx1, fmaxf(s[tt][j][2], s[tt][j][3]));
            }
            mx0 = fmaxf(mx0, __shfl_xor_sync(0xffffffffu, mx0, 1));
            mx0 = fmaxf(mx0, __shfl_xor_sync(0xffffffffu, mx0, 2));
            mx1 = fmaxf(mx1, __shfl_xor_sync(0xffffffffu, mx1, 1));
            mx1 = fmaxf(mx1, __shfl_xor_sync(0xffffffffu, mx1, 2));
            float mn0 = fmaxf(mrow[tt * 2], mx0), mn1 = fmaxf(mrow[tt * 2 + 1], mx1);
            float cr0 = exp2f(mrow[tt * 2] - mn0);
            float cr1 = exp2f(mrow[tt * 2 + 1] - mn1);
            float sum0 = 0.f, sum1 = 0.f;
            #pragma unroll
            for (int j = 0; j < 8; ++j) {
                uint32_t e0 = h2exp2(hpack(s[tt][j][0] - mn0, s[tt][j][1] - mn0));
                uint32_t e1 = h2exp2(hpack(s[tt][j][2] - mn1, s[tt][j][3] - mn1));
                pfrag[tt][j][0] = e0;
                pfrag[tt][j][1] = e1;
                float2 f0 = __half22float2(*(__half2*)&e0);
                float2 f1 = __half22float2(*(__half2*)&e1);
                sum0 += f0.x + f0.y;
                sum1 += f1.x + f1.y;
            }
            sum0 += __shfl_xor_sync(0xffffffffu, sum0, 1);
            sum0 += __shfl_xor_sync(0xffffffffu, sum0, 2);
            sum1 += __shfl_xor_sync(0xffffffffu, sum1, 1);
            sum1 += __shfl_xor_sync(0xffffffffu, sum1, 2);
            lrow[tt * 2] = lrow[tt * 2] * cr0 + sum0;
            lrow[tt * 2 + 1] = lrow[tt * 2 + 1] * cr1 + sum1;
            mrow[tt * 2] = mn0;
            mrow[tt * 2 + 1] = mn1;
            #pragma unroll
            for (int j = 0; j < 8; ++j) {
                acc[tt][j][0] *= cr0;
                acc[tt][j][1] *= cr0;
                acc[tt][j][2] *= cr1;
                acc[tt][j][3] *= cr1;
            }
        }

        // P (packed fp16 from exp) x V, V fragments via ldmatrix.x4
        #pragma unroll
        for (int kk = 0; kk < 4; ++kk) {
            #pragma unroll
            for (int jp = 0; jp < 4; ++jp) {
                uint32_t v0, v1, v2, v3;
                ldsm4(v0, v1, v2, v3,
                      vBase + (uint32_t)((jp * 16 * PB + kk * 16) * 2));
                mma_f16(acc[0][2 * jp],
                        pfrag[0][2 * kk][0], pfrag[0][2 * kk][1],
                        pfrag[0][2 * kk + 1][0], pfrag[0][2 * kk + 1][1], v0, v1);
                mma_f16(acc[1][2 * jp],
                        pfrag[1][2 * kk][0], pfrag[1][2 * kk][1],
                        pfrag[1][2 * kk + 1][0], pfrag[1][2 * kk + 1][1], v0, v1);
                mma_f16(acc[0][2 * jp + 1],
                        pfrag[0][2 * kk][0], pfrag[0][2 * kk][1],
                        pfrag[0][2 * kk + 1][0], pfrag[0][2 * kk + 1][1], v2, v3);
                mma_f16(acc[1][2 * jp + 1],
                        pfrag[1][2 * kk][0], pfrag[1][2 * kk][1],
                        pfrag[1][2 * kk + 1][0], pfrag[1][2 * kk + 1][1], v2, v3);
            }
        }
    }

    if (single) {
        // nc==1: normalize in-register and write fp32 output directly
        float inv0 = 1.f / lrow[0], inv1 = 1.f / lrow[1];
        float inv2 = 1.f / lrow[2], inv3 = 1.f / lrow[3];
        #pragma unroll
        for (int tt = 0; tt < 2; ++tt) {
            float ia = tt ? inv2 : inv0;
            float ib = tt ? inv3 : inv1;
            size_t row0 = (size_t)b * T_DIM + qRow + m0 + tt * 16 + g;
            #pragma unroll
            for (int j = 0; j < 8; ++j) {
                int col = 8 * j + 2 * t;
                *(float2*)&out[row0 * HS + col] =
                    make_float2(acc[tt][j][0] * ia, acc[tt][j][1] * ia);
                *(float2*)&out[(row0 + 8) * HS + col] =
                    make_float2(acc[tt][j][2] * ib, acc[tt][j][3] * ib);
            }
        }
        return;
    }

    // write partials (O as fp16; m in scaled-log2 domain)
    if (t == 0) {
        #pragma unroll
        for (int tt = 0; tt < 2; ++tt) {
            int r = m0 + tt * 16 + g;
            g_pm[(size_t)unit * QBLK + r] = mrow[tt * 2];
            g_pm[(size_t)unit * QBLK + r + 8] = mrow[tt * 2 + 1];
            g_pl[(size_t)unit * QBLK + r] = lrow[tt * 2];
            g_pl[(size_t)unit * QBLK + r + 8] = lrow[tt * 2 + 1];
        }
    }
    #pragma unroll
    for (int tt = 0; tt < 2; ++tt) {
        int r = m0 + tt * 16 + g;
        #pragma unroll
        for (int j = 0; j < 8; ++j) {
            int col = 8 * j + 2 * t;
            size_t pbase = ((size_t)unit * QBLK + r) * HS + col;
            *(uint32_t*)&g_po[pbase] = hpack(acc[tt][j][0], acc[tt][j][1]);
            *(uint32_t*)&g_po[pbase + 8 * HS] = hpack(acc[tt][j][2], acc[tt][j][3]);
        }
    }
}

// ---------------------------------------------------------------------------
// Combine fp16 partials for multi-chunk q-blocks only (mb >= 8).
// Grid (24, B, 8). m already in log2 domain.
// ---------------------------------------------------------------------------
__global__ __launch_bounds__(256) void reduce_kernel(float* __restrict__ out) {
    const int mb = blockIdx.x + 8, b = blockIdx.y;
    const int nc = (2 * mb + 2 + CBLK - 1) / CBLK;
    const int tid = threadIdx.x;
    const int r = tid >> 1;
    const int col = blockIdx.z * 8 + (tid & 1) * 4;
    const size_t ubase = ((size_t)(b * 32 + mb)) * NCHUNK;

    float m[NCHUNK], wgt[NCHUNK];
    float mstar = -1e30f;
    #pragma unroll
    for (int c = 0; c < NCHUNK; ++c) {
        if (c < nc) {
            m[c] = g_pm[(ubase + c) * QBLK + r];
            mstar = fmaxf(mstar, m[c]);
        }
    }
    float lsum = 0.f;
    #pragma unroll
    for (int c = 0; c < NCHUNK; ++c) {
        if (c < nc) {
            wgt[c] = exp2f(m[c] - mstar);
            lsum += wgt[c] * g_pl[(ubase + c) * QBLK + r];
        }
    }
    float inv = 1.f / lsum;

    float4 o = make_float4(0.f, 0.f, 0.f, 0.f);
    #pragma unroll
    for (int c = 0; c < NCHUNK; ++c) {
        if (c < nc) {
            uint2 pk = *(const uint2*)&g_po[((ubase + c) * QBLK + r) * HS + col];
            float2 p01 = __half22float2(*(__half2*)&pk.x);
            float2 p23 = __half22float2(*(__half2*)&pk.y);
            o.x += wgt[c] * p01.x;
            o.y += wgt[c] * p01.y;
            o.z += wgt[c] * p23.x;
            o.w += wgt[c] * p23.y;
        }
    }
    *(float4*)&out[((size_t)b * T_DIM + mb * QBLK + r) * HS + col] =
        make_float4(o.x * inv, o.y * inv, o.z * inv, o.w * inv);
}

extern "C" void kernel_launch(void* const* d_in, const int* in_sizes, int n_in,
                              void* d_out, int out_size) {
    const float* x = (const float*)d_in[0];
    const float* Wk = (const float*)d_in[1];
    const float* Wv = (const float*)d_in[2];
    float* out = (float*)d_out;

    const int smemProj = 3 * 64 * PB * sizeof(uint16_t);  // 27648
    const int smemAttn = NSTAGE * BUFBYTES;               // 55296
    cudaFuncSetAttribute(proj_kernel, cudaFuncAttributeMaxDynamicSharedMemorySize, smemProj);
    cudaFuncSetAttribute(attn_kernel, cudaFuncAttributeMaxDynamicSharedMemorySize, smemAttn);

    wconv_kernel<<<HS * D_DIM / 512, 256>>>(Wk, Wv);
    proj_kernel<<<(B_DIM * T_DIM) / 64, 128, smemProj>>>(x);
    attn_kernel<<<dim3(32, NCHUNK, B_DIM), 128, smemAttn>>>(out);
    reduce_kernel<<<dim3(24, B_DIM, 8), 256>>>(out);
}